// round 13
// baseline (speedup 1.0000x reference)
#include <cuda_runtime.h>
#include <cuda_bf16.h>
#include <cstdint>

// ---------------- scratch (static __device__, no allocations) ----------------
// n-major activation layout: [b][n][c*64+t], b-stride 1,024,000
__device__ __align__(16) float g_h[4][16384000];
__device__ __align__(16) float g_y0[16384000];
__device__ __align__(16) __nv_bfloat16 g_z1h[16384000];
__device__ __align__(16) __nv_bfloat16 g_z2h[16384000];
__device__ __align__(16) uint32_t g_Asp[2][256][512];   // bf16x2 k-pair packed A, zero-padded
__device__ float g_bnsum[32 * 16], g_bnsq[32 * 16];     // layer-0 stats (from x)
__device__ float g_bnS[2][32], g_bnQ[2][32];            // ping-pong fused stats (layers >= 1)
// fragment-packed tf32 weights for st_front MMA
__device__ __align__(16) uint32_t g_w1f[4][4][16][128]; // [l][mt][kc][lane*4+reg]  (GEMM1 A)
__device__ __align__(16) uint32_t g_w2f[4][6][4][128];  // [l][mt2][kc][lane*4+reg] (GEMM2 A = W2, M=96)

// ---------------- helpers ----------------
__device__ __forceinline__ uint32_t bf16x2_of(float lo, float hi) {
    uint32_t r; asm("cvt.rn.bf16x2.f32 %0,%1,%2;" : "=r"(r) : "f"(hi), "f"(lo)); return r;
}
__device__ __forceinline__ float to_tf32(float x) {
    asm("cvt.rna.tf32.f32 %0, %1;" : "=f"(x) : "f"(x));
    return x;
}
__device__ __forceinline__ uint32_t tf32_bits(float x) { return __float_as_uint(to_tf32(x)); }

__device__ __forceinline__ void mma_bf16(float& d0, float& d1, float& d2, float& d3,
                                         uint32_t a0, uint32_t a1, uint32_t a2, uint32_t a3,
                                         uint32_t b0, uint32_t b1) {
    asm volatile(
        "mma.sync.aligned.m16n8k16.row.col.f32.bf16.bf16.f32 "
        "{%0,%1,%2,%3},{%4,%5,%6,%7},{%8,%9},{%0,%1,%2,%3};"
        : "+f"(d0), "+f"(d1), "+f"(d2), "+f"(d3)
        : "r"(a0), "r"(a1), "r"(a2), "r"(a3), "r"(b0), "r"(b1));
}
__device__ __forceinline__ void mma_tf32(float& d0, float& d1, float& d2, float& d3,
                                         uint32_t a0, uint32_t a1, uint32_t a2, uint32_t a3,
                                         uint32_t b0, uint32_t b1) {
    asm volatile(
        "mma.sync.aligned.m16n8k8.row.col.f32.tf32.tf32.f32 "
        "{%0,%1,%2,%3},{%4,%5,%6,%7},{%8,%9},{%0,%1,%2,%3};"
        : "+f"(d0), "+f"(d1), "+f"(d2), "+f"(d3)
        : "r"(a0), "r"(a1), "r"(a2), "r"(a3), "r"(b0), "r"(b1));
}

// ---------------- weight packing ----------------
__global__ void prep_weights(const float* __restrict__ rw, const float* __restrict__ aw,
                             const float* __restrict__ gw, const float* __restrict__ gcw,
                             const float* __restrict__ A) {
    int tid = blockIdx.x * blockDim.x + threadIdx.x;
    int nt = gridDim.x * blockDim.x;

    // GEMM1 fragments. K order: k = 32*kk + c for conv taps kk=0..2; k = 96+c for res.
    for (int i = tid; i < 4 * 4 * 16 * 32; i += nt) {
        int l = i >> 11;
        int r = i & 2047;
        int mt = r >> 9;
        int r2 = r & 511;
        int kc = r2 >> 5;
        int lane = r2 & 31;
        int g = lane >> 2, tg = lane & 3;
        int o = mt * 8 + g;
        uint32_t* dst = &g_w1f[l][mt][kc][lane * 4];
#pragma unroll
        for (int half = 0; half < 2; half++) {
            int k = kc * 8 + tg + half * 4;
            int kk = k >> 5, c = k & 31;
            float va, vg;
            if (kk < 3) {
                va = aw[l * 3072 + o * 96 + c * 3 + kk];
                vg = gw[l * 3072 + o * 96 + c * 3 + kk];
            } else {
                va = rw[l * 1024 + o * 32 + c];
                vg = 0.f;
            }
            dst[half * 2 + 0] = tf32_bits(va);
            dst[half * 2 + 1] = tf32_bits(vg);
        }
    }
    // GEMM2 A fragments (W2, row-major M=96 x K=32)
    for (int i = tid; i < 4 * 6 * 4 * 32; i += nt) {
        int l = i / 768;
        int r = i % 768;
        int mt2 = r / 128;
        int r2 = r % 128;
        int kc = r2 >> 5;
        int lane = r2 & 31;
        int g = lane >> 2, tg = lane & 3;
        uint32_t* dst = &g_w2f[l][mt2][kc][lane * 4];
#pragma unroll
        for (int half = 0; half < 2; half++) {
            int k = kc * 8 + tg + half * 4;
#pragma unroll
            for (int rr = 0; rr < 2; rr++) {
                int o = mt2 * 16 + g + rr * 8;
                int grp = o >> 5, oo = o & 31;
                dst[half * 2 + rr] = tf32_bits(gcw[l * 3072 + oo * 96 + grp * 32 + k]);
            }
        }
    }
    // pack A supports into bf16x2 k-pairs
    for (int i = tid; i < 2 * 256 * 512; i += nt) {
        int e = i >> 17, kp = (i >> 9) & 255, m = i & 511;
        int v0 = 2 * kp, v1 = v0 + 1;
        float lo = (v0 < 500 && m < 500) ? A[(size_t)e * 250000 + (size_t)v0 * 500 + m] : 0.f;
        float hi = (v1 < 500 && m < 500) ? A[(size_t)e * 250000 + (size_t)v1 * 500 + m] : 0.f;
        g_Asp[e][kp][m] = bf16x2_of(lo, hi);
    }
}

// ---------------- batchnorm stats (input x only) ----------------
__global__ void bn_partial(const float* __restrict__ x) {
    int c = blockIdx.x, b = blockIdx.y;
    float s = 0.f, q = 0.f;
    const float* p = x + (size_t)(b * 32 + c) * 32000;
    for (int i = threadIdx.x; i < 8000; i += 256) {
        float4 v = __ldg((const float4*)(p + i * 4));
        s += v.x + v.y + v.z + v.w;
        q += v.x * v.x + v.y * v.y + v.z * v.z + v.w * v.w;
    }
    for (int o = 16; o; o >>= 1) {
        s += __shfl_down_sync(0xffffffffu, s, o);
        q += __shfl_down_sync(0xffffffffu, q, o);
    }
    __shared__ float ss[8], qq[8];
    int w = threadIdx.x >> 5;
    if ((threadIdx.x & 31) == 0) { ss[w] = s; qq[w] = q; }
    __syncthreads();
    if (threadIdx.x == 0) {
        float S = 0.f, Q = 0.f;
        for (int i = 0; i < 8; i++) { S += ss[i]; Q += qq[i]; }
        g_bnsum[c * 16 + b] = S;
        g_bnsq[c * 16 + b] = Q;
    }
}

// ---------------- st_front via tf32 tensor cores (bn finalize folded in) ----------------
__global__ __launch_bounds__(256) void st_front(
    const float* __restrict__ x, int layer,
    const float* __restrict__ gamma, const float* __restrict__ beta,
    const float* __restrict__ rb, const float* __restrict__ ab,
    const float* __restrict__ gb, const float* __restrict__ gcb) {
    __shared__ __align__(16) float ys[32][72];    // relu(bn(x)) at index t+2
    __shared__ __align__(16) float xs[32][72];    // raw x at index t+2
    __shared__ __align__(16) float x1C[32][72];   // x1: [c][t]
    __shared__ float s_scale[32], s_shift[32];

    int tid = threadIdx.x;
    int b = blockIdx.x / 500, n = blockIdx.x % 500;

    // bn finalize in-block
    if (tid < 32) {
        float S, Q;
        if (layer == 0) {
            S = 0.f; Q = 0.f;
#pragma unroll
            for (int bb2 = 0; bb2 < 16; bb2++) {
                S += g_bnsum[tid * 16 + bb2];
                Q += g_bnsq[tid * 16 + bb2];
            }
        } else {
            int pb = (layer - 1) & 1;
            S = g_bnS[pb][tid];
            Q = g_bnQ[pb][tid];
        }
        const float inv = 1.0f / 512000.0f;
        float m = S * inv;
        float var = Q * inv - m * m;
        float rstd = rsqrtf(var + 1e-5f);
        float sc = gamma[tid] * rstd;
        s_scale[tid] = sc;
        s_shift[tid] = beta[tid] - m * sc;
    }
    if (blockIdx.x == 0 && tid >= 32 && tid < 64) {
        g_bnS[layer & 1][tid - 32] = 0.f;
        g_bnQ[layer & 1][tid - 32] = 0.f;
    }
    if (tid < 64) ys[tid >> 1][tid & 1] = 0.f;   // left pads
    __syncthreads();

    if (layer == 0) {
        const float* xb = x + (size_t)b * 1024000 + n * 64;
#pragma unroll
        for (int it = 0; it < 2; it++) {
            int i = tid + it * 256;
            int c = i >> 4, tq = (i & 15) * 4;
            float4 v = __ldg((const float4*)(xb + (size_t)c * 32000 + tq));
            float sc = s_scale[c], sh = s_shift[c];
            float2 ya = { to_tf32(fmaxf(sc * v.x + sh, 0.f)), to_tf32(fmaxf(sc * v.y + sh, 0.f)) };
            float2 yb = { to_tf32(fmaxf(sc * v.z + sh, 0.f)), to_tf32(fmaxf(sc * v.w + sh, 0.f)) };
            *(float2*)&ys[c][tq + 2] = ya;
            *(float2*)&ys[c][tq + 4] = yb;
            float2 xa = { to_tf32(v.x), to_tf32(v.y) };
            float2 xb2 = { to_tf32(v.z), to_tf32(v.w) };
            *(float2*)&xs[c][tq + 2] = xa;
            *(float2*)&xs[c][tq + 4] = xb2;
        }
    } else {
        const float* hb = g_h[layer - 1] + ((size_t)b * 500 + n) * 2048;
#pragma unroll
        for (int it = 0; it < 2; it++) {
            int i = tid + it * 256;
            int c = i >> 4, tq = (i & 15) * 4;
            float4 v = *(const float4*)(hb + i * 4);
            float sc = s_scale[c], sh = s_shift[c];
            float2 ya = { to_tf32(fmaxf(sc * v.x + sh, 0.f)), to_tf32(fmaxf(sc * v.y + sh, 0.f)) };
            float2 yb = { to_tf32(fmaxf(sc * v.z + sh, 0.f)), to_tf32(fmaxf(sc * v.w + sh, 0.f)) };
            *(float2*)&ys[c][tq + 2] = ya;
            *(float2*)&ys[c][tq + 4] = yb;
            float2 xa = { to_tf32(v.x), to_tf32(v.y) };
            float2 xb2 = { to_tf32(v.z), to_tf32(v.w) };
            *(float2*)&xs[c][tq + 2] = xa;
            *(float2*)&xs[c][tq + 4] = xb2;
        }
    }
    __syncthreads();

    int lane = tid & 31, wid = tid >> 5;
    int g = lane >> 2, tig = lane & 3;
    int wm = wid & 3, wn = wid >> 2;
    int nbase = wn * 32;

    // ---- GEMM1 ----
    float c1[4][4];
#pragma unroll
    for (int s = 0; s < 4; s++)
#pragma unroll
        for (int k = 0; k < 4; k++) c1[s][k] = 0.f;

#pragma unroll
    for (int kc = 0; kc < 16; kc++) {
        uint4 af = __ldg((const uint4*)&g_w1f[layer][wm][kc][lane * 4]);
        int p = kc >> 2;
        int cb = (kc & 3) * 8;
        const float* base = (p < 3) ? &ys[cb][0] : &xs[cb][0];
        int off = (p < 3) ? p : 2;
#pragma unroll
        for (int s = 0; s < 4; s++) {
            int col = nbase + s * 8 + g + off;
            uint32_t b0 = __float_as_uint(base[tig * 72 + col]);
            uint32_t b1 = __float_as_uint(base[(tig + 4) * 72 + col]);
            mma_tf32(c1[s][0], c1[s][1], c1[s][2], c1[s][3],
                     af.x, af.y, af.z, af.w, b0, b1);
        }
    }

    // ---- x1 = tanh(aff+res+b) * sigmoid(gate+b); store as [c][t] ----
    {
        int o = wm * 8 + g;
        float abrb = __ldg(ab + o) + __ldg(rb + o);
        float gbv = __ldg(gb + o);
#pragma unroll
        for (int s = 0; s < 4; s++) {
            int col = nbase + s * 8 + 2 * tig;
            float v0 = tanhf(c1[s][0] + abrb) * (1.f / (1.f + expf(-(c1[s][2] + gbv))));
            float v1 = tanhf(c1[s][1] + abrb) * (1.f / (1.f + expf(-(c1[s][3] + gbv))));
            float2 pr = { to_tf32(v0), to_tf32(v1) };
            *(float2*)&x1C[o][col] = pr;
        }
    }
    __syncthreads();

    // ---- GEMM2: C[96 o][64 t] = W2 * x1C (warps 0..5) ----
    if (wid < 6) {
        float c2[8][4];
#pragma unroll
        for (int s = 0; s < 8; s++)
#pragma unroll
            for (int k = 0; k < 4; k++) c2[s][k] = 0.f;

#pragma unroll
        for (int kc = 0; kc < 4; kc++) {
            uint4 af = __ldg((const uint4*)&g_w2f[layer][wid][kc][lane * 4]);
#pragma unroll
            for (int s = 0; s < 8; s++) {
                int col = s * 8 + g;
                uint32_t b0 = __float_as_uint(x1C[kc * 8 + tig][col]);
                uint32_t b1 = __float_as_uint(x1C[kc * 8 + tig + 4][col]);
                mma_tf32(c2[s][0], c2[s][1], c2[s][2], c2[s][3],
                         af.x, af.y, af.z, af.w, b0, b1);
            }
        }

        size_t obase = ((size_t)b * 500 + n) * 2048;
        int o0 = wid * 16 + g, o1 = o0 + 8;
        if (wid < 2) {
            float bz0 = __ldg(gcb + o0), bz1 = __ldg(gcb + o1);
#pragma unroll
            for (int s = 0; s < 8; s++) {
                int t = s * 8 + 2 * tig;
                float2 r0 = { c2[s][0] + bz0, c2[s][1] + bz0 };
                float2 r1 = { c2[s][2] + bz1, c2[s][3] + bz1 };
                *(float2*)(g_y0 + obase + (size_t)o0 * 64 + t) = r0;
                *(float2*)(g_y0 + obase + (size_t)o1 * 64 + t) = r1;
            }
        } else if (wid < 4) {
            int z0 = o0 - 32, z1r = o1 - 32;
#pragma unroll
            for (int s = 0; s < 8; s++) {
                int t = s * 8 + 2 * tig;
                *(uint32_t*)(g_z1h + obase + (size_t)z0 * 64 + t) = bf16x2_of(c2[s][0], c2[s][1]);
                *(uint32_t*)(g_z1h + obase + (size_t)z1r * 64 + t) = bf16x2_of(c2[s][2], c2[s][3]);
            }
        } else {
            int z0 = o0 - 64, z1r = o1 - 64;
#pragma unroll
            for (int s = 0; s < 8; s++) {
                int t = s * 8 + 2 * tig;
                *(uint32_t*)(g_z2h + obase + (size_t)z0 * 64 + t) = bf16x2_of(c2[s][0], c2[s][1]);
                *(uint32_t*)(g_z2h + obase + (size_t)z1r * 64 + t) = bf16x2_of(c2[s][2], c2[s][3]);
            }
        }
    }
}

// ---------------- graph diffusion with bf16 tensor cores (register-staged pipeline) ----------------
__global__ __launch_bounds__(256) void graph_mma(int layer) {
    __shared__ __align__(16) uint32_t Asp[2][16][136];
    __shared__ __align__(16) uint32_t Zsp[2][16][136];

    int tid = threadIdx.x;
    int m0 = blockIdx.x * 128;
    int n0 = blockIdx.y * 128;
    int bb = blockIdx.z;
    int lane = tid & 31, wid = tid >> 5;
    int wm = wid & 1, wn = wid >> 1;
    int mbase = wm * 64, nbase = wn * 32;
    int g = lane >> 2, tig = lane & 3;

    int r = tid >> 4;
    int seg = (tid & 15) * 8;

    float acc[4][4][4];
#pragma unroll
    for (int i = 0; i < 4; i++)
#pragma unroll
        for (int j = 0; j < 4; j++)
#pragma unroll
            for (int k = 0; k < 4; k++) acc[i][j][k] = 0.f;

    uint4 pa0, pa1, plo, phi;   // staging registers

    auto ldg_stage = [&](int st) {
        int e = st >> 4, s = st & 15;
        int kpg = s * 16 + r;
        const uint4* ap = (const uint4*)&g_Asp[e][kpg][m0 + seg];
        pa0 = __ldg(ap);
        pa1 = __ldg(ap + 1);
        int v0 = 2 * kpg, v1 = v0 + 1;
        const __nv_bfloat16* zb = e ? g_z2h : g_z1h;
        size_t zoff = (size_t)bb * 1024000 + n0 + seg;
        plo = make_uint4(0, 0, 0, 0);
        phi = make_uint4(0, 0, 0, 0);
        if (v0 < 500) plo = *(const uint4*)(zb + zoff + (size_t)v0 * 2048);
        if (v1 < 500) phi = *(const uint4*)(zb + zoff + (size_t)v1 * 2048);
    };
    auto sts_stage = [&](int buf) {
        *(uint4*)&Asp[buf][r][seg]     = pa0;
        *(uint4*)&Asp[buf][r][seg + 4] = pa1;
        uint4 o0, o1;
        o0.x = __byte_perm(plo.x, phi.x, 0x5410); o0.y = __byte_perm(plo.x, phi.x, 0x7632);
        o0.z = __byte_perm(plo.y, phi.y, 0x5410); o0.w = __byte_perm(plo.y, phi.y, 0x7632);
        o1.x = __byte_perm(plo.z, phi.z, 0x5410); o1.y = __byte_perm(plo.z, phi.z, 0x7632);
        o1.z = __byte_perm(plo.w, phi.w, 0x5410); o1.w = __byte_perm(plo.w, phi.w, 0x7632);
        *(uint4*)&Zsp[buf][r][seg]     = o0;
        *(uint4*)&Zsp[buf][r][seg + 4] = o1;
    };

    ldg_stage(0);
    sts_stage(0);
    __syncthreads();

    for (int st = 0; st < 32; st++) {
        int cur = st & 1;
        if (st + 1 < 32) ldg_stage(st + 1);   // issue LDGs before compute
#pragma unroll
        for (int ch = 0; ch < 2; ch++) {
            int k0 = ch * 8;
            uint32_t bfr[4][2];
#pragma unroll
            for (int nt = 0; nt < 4; nt++) {
                bfr[nt][0] = Zsp[cur][k0 + tig][nbase + nt * 8 + g];
                bfr[nt][1] = Zsp[cur][k0 + tig + 4][nbase + nt * 8 + g];
            }
#pragma unroll
            for (int mt = 0; mt < 4; mt++) {
                int mr = mbase + mt * 16 + g;
                uint32_t a0 = Asp[cur][k0 + tig][mr];
                uint32_t a1 = Asp[cur][k0 + tig][mr + 8];
                uint32_t a2 = Asp[cur][k0 + tig + 4][mr];
                uint32_t a3 = Asp[cur][k0 + tig + 4][mr + 8];
#pragma unroll
                for (int nt = 0; nt < 4; nt++)
                    mma_bf16(acc[mt][nt][0], acc[mt][nt][1], acc[mt][nt][2], acc[mt][nt][3],
                             a0, a1, a2, a3, bfr[nt][0], bfr[nt][1]);
            }
        }
        if (st + 1 < 32) sts_stage(cur ^ 1);  // drain LDGs into smem after compute
        __syncthreads();
    }

    float* hout = g_h[layer];
    size_t bbase = (size_t)bb * 1024000;
    float s = 0.f, q = 0.f;
#pragma unroll
    for (int mt = 0; mt < 4; mt++) {
#pragma unroll
        for (int nt = 0; nt < 4; nt++) {
            int w0 = m0 + mbase + mt * 16 + g;
            int j = n0 + nbase + nt * 8 + 2 * tig;
            if (w0 < 500) {
                size_t idx = bbase + (size_t)w0 * 2048 + j;
                float2 y = *(const float2*)(g_y0 + idx);
                float2 rres;
                rres.x = acc[mt][nt][0] + y.x;
                rres.y = acc[mt][nt][1] + y.y;
                *(float2*)(hout + idx) = rres;
                s += rres.x + rres.y;
                q += rres.x * rres.x + rres.y * rres.y;
            }
            if (w0 + 8 < 500) {
                size_t idx = bbase + (size_t)(w0 + 8) * 2048 + j;
                float2 y = *(const float2*)(g_y0 + idx);
                float2 rres;
                rres.x = acc[mt][nt][2] + y.x;
                rres.y = acc[mt][nt][3] + y.y;
                *(float2*)(hout + idx) = rres;
                s += rres.x + rres.y;
                q += rres.x * rres.x + rres.y * rres.y;
            }
        }
    }
    for (int o = 16; o; o >>= 1) {
        s += __shfl_down_sync(0xffffffffu, s, o);
        q += __shfl_down_sync(0xffffffffu, q, o);
    }
    if (lane == 0) {
        int cw = (n0 + nbase) >> 6;
        atomicAdd(&g_bnS[layer & 1][cw], s);
        atomicAdd(&g_bnQ[layer & 1][cw], q);
    }
}

// ---------------- fused attention: logits + softmax + weighted sum (round-9 design) ----------------
// dyn smem floats: vbuf[5][32][72] | e1s[64][72] | red[4][64] | lgs[5][64]  = 16704 fl
__global__ __launch_bounds__(256) void attn_fused(
    const float* __restrict__ x,
    const float* __restrict__ w1, const float* __restrict__ b1,
    const float* __restrict__ w2, const float* __restrict__ b2,
    const float* __restrict__ w3,
    float* __restrict__ out) {
    extern __shared__ float sm[];
    float* vbuf = sm;                // 5 x 2304 (32 rows x 72)
    float* e1s  = sm + 11520;        // 64 x 72
    float* red  = sm + 16128;        // 4 x 64
    float* lgs  = sm + 16384;        // 5 x 64

    int tid = threadIdx.x;
    int b = blockIdx.x / 500, n = blockIdx.x % 500;
    int lane = tid & 31, wid = tid >> 5;
    int wm = wid & 3;
    int wn = wid >> 2;
    int g = lane >> 2, tig = lane & 3;

    uint32_t a1f[4][4], a2f[8][4];
#pragma unroll
    for (int kk = 0; kk < 4; kk++) {
        a1f[kk][0] = tf32_bits(__ldg(w1 + (wm * 16 + g) * 32 + kk * 8 + tig));
        a1f[kk][1] = tf32_bits(__ldg(w1 + (wm * 16 + g + 8) * 32 + kk * 8 + tig));
        a1f[kk][2] = tf32_bits(__ldg(w1 + (wm * 16 + g) * 32 + kk * 8 + tig + 4));
        a1f[kk][3] = tf32_bits(__ldg(w1 + (wm * 16 + g + 8) * 32 + kk * 8 + tig + 4));
    }
#pragma unroll
    for (int kk = 0; kk < 8; kk++) {
        a2f[kk][0] = tf32_bits(__ldg(w2 + (wm * 16 + g) * 64 + kk * 8 + tig));
        a2f[kk][1] = tf32_bits(__ldg(w2 + (wm * 16 + g + 8) * 64 + kk * 8 + tig));
        a2f[kk][2] = tf32_bits(__ldg(w2 + (wm * 16 + g) * 64 + kk * 8 + tig + 4));
        a2f[kk][3] = tf32_bits(__ldg(w2 + (wm * 16 + g + 8) * 64 + kk * 8 + tig + 4));
    }
    float b1r0 = b1[wm * 16 + g], b1r1 = b1[wm * 16 + g + 8];
    float b2r0 = b2[wm * 16 + g], b2r1 = b2[wm * 16 + g + 8];
    float w3r0 = w3[wm * 16 + g], w3r1 = w3[wm * 16 + g + 8];

    for (int l = 0; l < 5; l++) {
        float* vb = vbuf + l * 2304;
        __syncthreads();
        if (l == 0) {
            const float* xb = x + (size_t)b * 1024000 + n * 64;
#pragma unroll
            for (int it = 0; it < 2; it++) {
                int i = tid + it * 256;
                int c = i >> 4, tq = (i & 15) * 4;
                float4 v = __ldg((const float4*)(xb + (size_t)c * 32000 + tq));
                float4 rv = { fmaxf(v.x, 0.f), fmaxf(v.y, 0.f), fmaxf(v.z, 0.f), fmaxf(v.w, 0.f) };
                *(float4*)&vb[c * 72 + tq] = rv;
            }
        } else {
            const float* hb = g_h[l - 1] + ((size_t)b * 500 + n) * 2048;
#pragma unroll
            for (int it = 0; it < 2; it++) {
                int i = tid + it * 256;
                int c = i >> 4, tq = (i & 15) * 4;
                float4 v = *(const float4*)(hb + i * 4);
                float4 rv = { fmaxf(v.x, 0.f), fmaxf(v.y, 0.f), fmaxf(v.z, 0.f), fmaxf(v.w, 0.f) };
                *(float4*)&vb[c * 72 + tq] = rv;
            }
        }
        __syncthreads();

        float c1[4][4];
#pragma unroll
        for (int sub = 0; sub < 4; sub++)
#pragma unroll
            for (int k = 0; k < 4; k++) c1[sub][k] = 0.f;
#pragma unroll
        for (int kk = 0; kk < 4; kk++) {
#pragma unroll
            for (int sub = 0; sub < 4; sub++) {
                int col = wn * 32 + sub * 8 + g;
                uint32_t bb0 = tf32_bits(vb[(kk * 8 + tig) * 72 + col]);
                uint32_t bb1 = tf32_bits(vb[(kk * 8 + tig + 4) * 72 + col]);
                mma_tf32(c1[sub][0], c1[sub][1], c1[sub][2], c1[sub][3],
                         a1f[kk][0], a1f[kk][1], a1f[kk][2], a1f[kk][3], bb0, bb1);
            }
        }
#pragma unroll
        for (int sub = 0; sub < 4; sub++) {
            int col = wn * 32 + sub * 8 + 2 * tig;
            e1s[(wm * 16 + g) * 72 + col]     = to_tf32(fmaxf(c1[sub][0] + b1r0, 0.f));
            e1s[(wm * 16 + g) * 72 + col + 1] = to_tf32(fmaxf(c1[sub][1] + b1r0, 0.f));
            e1s[(wm * 16 + g + 8) * 72 + col]     = to_tf32(fmaxf(c1[sub][2] + b1r1, 0.f));
            e1s[(wm * 16 + g + 8) * 72 + col + 1] = to_tf32(fmaxf(c1[sub][3] + b1r1, 0.f));
        }
        __syncthreads();

        float c2[4][4];
#pragma unroll
        for (int sub = 0; sub < 4; sub++)
#pragma unroll
            for (int k = 0; k < 4; k++) c2[sub][k] = 0.f;
#pragma unroll
        for (int kk = 0; kk < 8; kk++) {
#pragma unroll
            for (int sub = 0; sub < 4; sub++) {
                int col = wn * 32 + sub * 8 + g;
                uint32_t bb0 = __float_as_uint(e1s[(kk * 8 + tig) * 72 + col]);
                uint32_t bb1 = __float_as_uint(e1s[(kk * 8 + tig + 4) * 72 + col]);
                mma_tf32(c2[sub][0], c2[sub][1], c2[sub][2], c2[sub][3],
                         a2f[kk][0], a2f[kk][1], a2f[kk][2], a2f[kk][3], bb0, bb1);
            }
        }
        float p[4][2];
#pragma unroll
        for (int sub = 0; sub < 4; sub++) {
            p[sub][0] = w3r0 * fmaxf(c2[sub][0] + b2r0, 0.f) + w3r1 * fmaxf(c2[sub][2] + b2r1, 0.f);
            p[sub][1] = w3r0 * fmaxf(c2[sub][1] + b2r0, 0.f) + w3r1 * fmaxf(c2[sub][3] + b2r1, 0.f);
        }
#pragma unroll
        for (int off = 4; off <= 16; off <<= 1) {
#pragma unroll
            for (int sub = 0; sub < 4; sub++) {
                p[sub][0] += __shfl_xor_sync(0xffffffffu, p[sub][0], off);
                p[sub][1] += __shfl_xor_sync(0xffffffffu, p[sub][1], off);
            }
        }
        if (g == 0) {
#pragma unroll
            for (int sub = 0; sub < 4; sub++) {
                int col = wn * 32 + sub * 8 + 2 * tig;
                red[wm * 64 + col] = p[sub][0];
                red[wm * 64 + col + 1] = p[sub][1];
            }
        }
        __syncthreads();
        if (tid < 64)
            lgs[l * 64 + tid] = red[tid] + red[64 + tid] + red[128 + tid] + red[192 + tid];
    }
    __syncthreads();

    if (tid < 64) {
        float lg[5];
        float m = -1e30f;
#pragma unroll
        for (int l = 0; l < 5; l++) {
            lg[l] = lgs[l * 64 + tid];
            m = fmaxf(m, lg[l]);
        }
        float s = 0.f;
#pragma unroll
        for (int l = 0; l < 5; l++) { lg[l] = expf(lg[l] - m); s += lg[l]; }
        float inv = 1.f / s;
#pragma unroll
        for (int l = 0; l < 5; l++) lgs[l * 64 + tid] = lg[l] * inv;
    }
    __syncthreads();

    for (int i = tid; i < 2048; i += 256) {
        int c = i >> 6, t = i & 63;
        float s = lgs[t] * vbuf[c * 72 + t];
        s += lgs[64 + t]  * vbuf[2304 + c * 72 + t];
        s += lgs[128 + t] * vbuf[4608 + c * 72 + t];
        s += lgs[192 + t] * vbuf[6912 + c * 72 + t];
        s += lgs[256 + t] * vbuf[9216 + c * 72 + t];
        out[((size_t)(b * 32 + c) * 500 + n) * 64 + t] = s;
    }
}

// ---------------- launch ----------------
extern "C" void kernel_launch(void* const* d_in, const int* in_sizes, int n_in,
                              void* d_out, int out_size) {
    (void)in_sizes; (void)n_in; (void)out_size;
    const float* x        = (const float*)d_in[0];
    const float* supports = (const float*)d_in[1];
    const float* bn_gamma = (const float*)d_in[2];
    const float* bn_beta  = (const float*)d_in[3];
    const float* res_w    = (const float*)d_in[4];
    const float* res_b    = (const float*)d_in[5];
    const float* aff_w    = (const float*)d_in[6];
    const float* aff_b    = (const float*)d_in[7];
    const float* gate_w   = (const float*)d_in[8];
    const float* gate_b   = (const float*)d_in[9];
    const float* gc_w     = (const float*)d_in[10];
    const float* gc_b     = (const float*)d_in[11];
    const float* attn_w1  = (const float*)d_in[12];
    const float* attn_b1  = (const float*)d_in[13];
    const float* attn_w2  = (const float*)d_in[14];
    const float* attn_b2  = (const float*)d_in[15];
    const float* attn_w3  = (const float*)d_in[16];
    float* out = (float*)d_out;

    cudaFuncSetAttribute(attn_fused, cudaFuncAttributeMaxDynamicSharedMemorySize, 66816);

    prep_weights<<<64, 256>>>(res_w, aff_w, gate_w, gc_w, supports);
    bn_partial<<<dim3(32, 16), 256>>>(x);

    for (int l = 0; l < 4; l++) {
        st_front<<<8000, 256>>>(x, l, bn_gamma + l * 32, bn_beta + l * 32,
                                res_b + l * 32, aff_b + l * 32,
                                gate_b + l * 32, gc_b + l * 32);
        graph_mma<<<dim3(4, 16, 16), 256>>>(l);
    }
    attn_fused<<<8000, 256, 66816>>>(x, attn_w1, attn_b1, attn_w2, attn_b2, attn_w3, out);
}

// round 14
// speedup vs baseline: 1.2601x; 1.2601x over previous
#include <cuda_runtime.h>
#include <cuda_bf16.h>
#include <cstdint>

// ---------------- scratch (static __device__, no allocations) ----------------
// n-major activation layout: [b][n][c*64+t], b-stride 1,024,000
__device__ __align__(16) float g_h[4][16384000];
__device__ __align__(16) float g_y0[16384000];
__device__ __align__(16) __nv_bfloat16 g_z1h[16384000];
__device__ __align__(16) __nv_bfloat16 g_z2h[16384000];
__device__ __align__(16) uint32_t g_Asp[2][256][512];   // bf16x2 k-pair packed A, zero-padded
__device__ float g_bnsum[32 * 16], g_bnsq[32 * 16];     // layer-0 stats (from x)
__device__ float g_bnS[2][32], g_bnQ[2][32];            // ping-pong fused stats (layers >= 1)
// fragment-packed tf32 weights for st_front MMA
__device__ __align__(16) uint32_t g_w1f[4][4][16][128]; // [l][mt][kc][lane*4+reg]  (GEMM1 A)
__device__ __align__(16) uint32_t g_w2f[4][6][4][128];  // [l][mt2][kc][lane*4+reg] (GEMM2 A = W2, M=96)

// ---------------- helpers ----------------
__device__ __forceinline__ uint32_t bf16x2_of(float lo, float hi) {
    uint32_t r; asm("cvt.rn.bf16x2.f32 %0,%1,%2;" : "=r"(r) : "f"(hi), "f"(lo)); return r;
}
__device__ __forceinline__ float to_tf32(float x) {
    asm("cvt.rna.tf32.f32 %0, %1;" : "=f"(x) : "f"(x));
    return x;
}
__device__ __forceinline__ uint32_t tf32_bits(float x) { return __float_as_uint(to_tf32(x)); }

__device__ __forceinline__ void mma_bf16(float& d0, float& d1, float& d2, float& d3,
                                         uint32_t a0, uint32_t a1, uint32_t a2, uint32_t a3,
                                         uint32_t b0, uint32_t b1) {
    asm volatile(
        "mma.sync.aligned.m16n8k16.row.col.f32.bf16.bf16.f32 "
        "{%0,%1,%2,%3},{%4,%5,%6,%7},{%8,%9},{%0,%1,%2,%3};"
        : "+f"(d0), "+f"(d1), "+f"(d2), "+f"(d3)
        : "r"(a0), "r"(a1), "r"(a2), "r"(a3), "r"(b0), "r"(b1));
}
__device__ __forceinline__ void mma_tf32(float& d0, float& d1, float& d2, float& d3,
                                         uint32_t a0, uint32_t a1, uint32_t a2, uint32_t a3,
                                         uint32_t b0, uint32_t b1) {
    asm volatile(
        "mma.sync.aligned.m16n8k8.row.col.f32.tf32.tf32.f32 "
        "{%0,%1,%2,%3},{%4,%5,%6,%7},{%8,%9},{%0,%1,%2,%3};"
        : "+f"(d0), "+f"(d1), "+f"(d2), "+f"(d3)
        : "r"(a0), "r"(a1), "r"(a2), "r"(a3), "r"(b0), "r"(b1));
}

// ---------------- weight packing ----------------
__global__ void prep_weights(const float* __restrict__ rw, const float* __restrict__ aw,
                             const float* __restrict__ gw, const float* __restrict__ gcw,
                             const float* __restrict__ A) {
    int tid = blockIdx.x * blockDim.x + threadIdx.x;
    int nt = gridDim.x * blockDim.x;

    // GEMM1 fragments. K order: k = 32*kk + c for conv taps kk=0..2; k = 96+c for res.
    for (int i = tid; i < 4 * 4 * 16 * 32; i += nt) {
        int l = i >> 11;
        int r = i & 2047;
        int mt = r >> 9;
        int r2 = r & 511;
        int kc = r2 >> 5;
        int lane = r2 & 31;
        int g = lane >> 2, tg = lane & 3;
        int o = mt * 8 + g;
        uint32_t* dst = &g_w1f[l][mt][kc][lane * 4];
#pragma unroll
        for (int half = 0; half < 2; half++) {
            int k = kc * 8 + tg + half * 4;
            int kk = k >> 5, c = k & 31;
            float va, vg;
            if (kk < 3) {
                va = aw[l * 3072 + o * 96 + c * 3 + kk];
                vg = gw[l * 3072 + o * 96 + c * 3 + kk];
            } else {
                va = rw[l * 1024 + o * 32 + c];
                vg = 0.f;
            }
            dst[half * 2 + 0] = tf32_bits(va);
            dst[half * 2 + 1] = tf32_bits(vg);
        }
    }
    // GEMM2 A fragments (W2, row-major M=96 x K=32)
    for (int i = tid; i < 4 * 6 * 4 * 32; i += nt) {
        int l = i / 768;
        int r = i % 768;
        int mt2 = r / 128;
        int r2 = r % 128;
        int kc = r2 >> 5;
        int lane = r2 & 31;
        int g = lane >> 2, tg = lane & 3;
        uint32_t* dst = &g_w2f[l][mt2][kc][lane * 4];
#pragma unroll
        for (int half = 0; half < 2; half++) {
            int k = kc * 8 + tg + half * 4;
#pragma unroll
            for (int rr = 0; rr < 2; rr++) {
                int o = mt2 * 16 + g + rr * 8;
                int grp = o >> 5, oo = o & 31;
                dst[half * 2 + rr] = tf32_bits(gcw[l * 3072 + oo * 96 + grp * 32 + k]);
            }
        }
    }
    // pack A supports into bf16x2 k-pairs
    for (int i = tid; i < 2 * 256 * 512; i += nt) {
        int e = i >> 17, kp = (i >> 9) & 255, m = i & 511;
        int v0 = 2 * kp, v1 = v0 + 1;
        float lo = (v0 < 500 && m < 500) ? A[(size_t)e * 250000 + (size_t)v0 * 500 + m] : 0.f;
        float hi = (v1 < 500 && m < 500) ? A[(size_t)e * 250000 + (size_t)v1 * 500 + m] : 0.f;
        g_Asp[e][kp][m] = bf16x2_of(lo, hi);
    }
}

// ---------------- batchnorm stats (input x only) ----------------
__global__ void bn_partial(const float* __restrict__ x) {
    int c = blockIdx.x, b = blockIdx.y;
    float s = 0.f, q = 0.f;
    const float* p = x + (size_t)(b * 32 + c) * 32000;
    for (int i = threadIdx.x; i < 8000; i += 256) {
        float4 v = __ldg((const float4*)(p + i * 4));
        s += v.x + v.y + v.z + v.w;
        q += v.x * v.x + v.y * v.y + v.z * v.z + v.w * v.w;
    }
    for (int o = 16; o; o >>= 1) {
        s += __shfl_down_sync(0xffffffffu, s, o);
        q += __shfl_down_sync(0xffffffffu, q, o);
    }
    __shared__ float ss[8], qq[8];
    int w = threadIdx.x >> 5;
    if ((threadIdx.x & 31) == 0) { ss[w] = s; qq[w] = q; }
    __syncthreads();
    if (threadIdx.x == 0) {
        float S = 0.f, Q = 0.f;
        for (int i = 0; i < 8; i++) { S += ss[i]; Q += qq[i]; }
        g_bnsum[c * 16 + b] = S;
        g_bnsq[c * 16 + b] = Q;
    }
}

// ---------------- st_front via tf32 tensor cores (bn finalize folded in) ----------------
__global__ __launch_bounds__(256) void st_front(
    const float* __restrict__ x, int layer,
    const float* __restrict__ gamma, const float* __restrict__ beta,
    const float* __restrict__ rb, const float* __restrict__ ab,
    const float* __restrict__ gb, const float* __restrict__ gcb) {
    __shared__ __align__(16) float ys[32][72];    // relu(bn(x)) at index t+2
    __shared__ __align__(16) float xs[32][72];    // raw x at index t+2
    __shared__ __align__(16) float x1C[32][72];   // x1: [c][t]
    __shared__ float s_scale[32], s_shift[32];

    int tid = threadIdx.x;
    int b = blockIdx.x / 500, n = blockIdx.x % 500;

    // bn finalize in-block
    if (tid < 32) {
        float S, Q;
        if (layer == 0) {
            S = 0.f; Q = 0.f;
#pragma unroll
            for (int bb2 = 0; bb2 < 16; bb2++) {
                S += g_bnsum[tid * 16 + bb2];
                Q += g_bnsq[tid * 16 + bb2];
            }
        } else {
            int pb = (layer - 1) & 1;
            S = g_bnS[pb][tid];
            Q = g_bnQ[pb][tid];
        }
        const float inv = 1.0f / 512000.0f;
        float m = S * inv;
        float var = Q * inv - m * m;
        float rstd = rsqrtf(var + 1e-5f);
        float sc = gamma[tid] * rstd;
        s_scale[tid] = sc;
        s_shift[tid] = beta[tid] - m * sc;
    }
    if (blockIdx.x == 0 && tid >= 32 && tid < 64) {
        g_bnS[layer & 1][tid - 32] = 0.f;
        g_bnQ[layer & 1][tid - 32] = 0.f;
    }
    if (tid < 64) ys[tid >> 1][tid & 1] = 0.f;   // left pads
    __syncthreads();

    if (layer == 0) {
        const float* xb = x + (size_t)b * 1024000 + n * 64;
#pragma unroll
        for (int it = 0; it < 2; it++) {
            int i = tid + it * 256;
            int c = i >> 4, tq = (i & 15) * 4;
            float4 v = __ldg((const float4*)(xb + (size_t)c * 32000 + tq));
            float sc = s_scale[c], sh = s_shift[c];
            float2 ya = { to_tf32(fmaxf(sc * v.x + sh, 0.f)), to_tf32(fmaxf(sc * v.y + sh, 0.f)) };
            float2 yb = { to_tf32(fmaxf(sc * v.z + sh, 0.f)), to_tf32(fmaxf(sc * v.w + sh, 0.f)) };
            *(float2*)&ys[c][tq + 2] = ya;
            *(float2*)&ys[c][tq + 4] = yb;
            float2 xa = { to_tf32(v.x), to_tf32(v.y) };
            float2 xb2 = { to_tf32(v.z), to_tf32(v.w) };
            *(float2*)&xs[c][tq + 2] = xa;
            *(float2*)&xs[c][tq + 4] = xb2;
        }
    } else {
        const float* hb = g_h[layer - 1] + ((size_t)b * 500 + n) * 2048;
#pragma unroll
        for (int it = 0; it < 2; it++) {
            int i = tid + it * 256;
            int c = i >> 4, tq = (i & 15) * 4;
            float4 v = *(const float4*)(hb + i * 4);
            float sc = s_scale[c], sh = s_shift[c];
            float2 ya = { to_tf32(fmaxf(sc * v.x + sh, 0.f)), to_tf32(fmaxf(sc * v.y + sh, 0.f)) };
            float2 yb = { to_tf32(fmaxf(sc * v.z + sh, 0.f)), to_tf32(fmaxf(sc * v.w + sh, 0.f)) };
            *(float2*)&ys[c][tq + 2] = ya;
            *(float2*)&ys[c][tq + 4] = yb;
            float2 xa = { to_tf32(v.x), to_tf32(v.y) };
            float2 xb2 = { to_tf32(v.z), to_tf32(v.w) };
            *(float2*)&xs[c][tq + 2] = xa;
            *(float2*)&xs[c][tq + 4] = xb2;
        }
    }
    __syncthreads();

    int lane = tid & 31, wid = tid >> 5;
    int g = lane >> 2, tig = lane & 3;
    int wm = wid & 3, wn = wid >> 2;
    int nbase = wn * 32;

    // ---- GEMM1 ----
    float c1[4][4];
#pragma unroll
    for (int s = 0; s < 4; s++)
#pragma unroll
        for (int k = 0; k < 4; k++) c1[s][k] = 0.f;

#pragma unroll
    for (int kc = 0; kc < 16; kc++) {
        uint4 af = __ldg((const uint4*)&g_w1f[layer][wm][kc][lane * 4]);
        int p = kc >> 2;
        int cb = (kc & 3) * 8;
        const float* base = (p < 3) ? &ys[cb][0] : &xs[cb][0];
        int off = (p < 3) ? p : 2;
#pragma unroll
        for (int s = 0; s < 4; s++) {
            int col = nbase + s * 8 + g + off;
            uint32_t b0 = __float_as_uint(base[tig * 72 + col]);
            uint32_t b1 = __float_as_uint(base[(tig + 4) * 72 + col]);
            mma_tf32(c1[s][0], c1[s][1], c1[s][2], c1[s][3],
                     af.x, af.y, af.z, af.w, b0, b1);
        }
    }

    // ---- x1 = tanh(aff+res+b) * sigmoid(gate+b); store as [c][t] ----
    {
        int o = wm * 8 + g;
        float abrb = __ldg(ab + o) + __ldg(rb + o);
        float gbv = __ldg(gb + o);
#pragma unroll
        for (int s = 0; s < 4; s++) {
            int col = nbase + s * 8 + 2 * tig;
            float v0 = tanhf(c1[s][0] + abrb) * (1.f / (1.f + expf(-(c1[s][2] + gbv))));
            float v1 = tanhf(c1[s][1] + abrb) * (1.f / (1.f + expf(-(c1[s][3] + gbv))));
            float2 pr = { to_tf32(v0), to_tf32(v1) };
            *(float2*)&x1C[o][col] = pr;
        }
    }
    __syncthreads();

    // ---- GEMM2: C[96 o][64 t] = W2 * x1C (warps 0..5) ----
    if (wid < 6) {
        float c2[8][4];
#pragma unroll
        for (int s = 0; s < 8; s++)
#pragma unroll
            for (int k = 0; k < 4; k++) c2[s][k] = 0.f;

#pragma unroll
        for (int kc = 0; kc < 4; kc++) {
            uint4 af = __ldg((const uint4*)&g_w2f[layer][wid][kc][lane * 4]);
#pragma unroll
            for (int s = 0; s < 8; s++) {
                int col = s * 8 + g;
                uint32_t b0 = __float_as_uint(x1C[kc * 8 + tig][col]);
                uint32_t b1 = __float_as_uint(x1C[kc * 8 + tig + 4][col]);
                mma_tf32(c2[s][0], c2[s][1], c2[s][2], c2[s][3],
                         af.x, af.y, af.z, af.w, b0, b1);
            }
        }

        size_t obase = ((size_t)b * 500 + n) * 2048;
        int o0 = wid * 16 + g, o1 = o0 + 8;
        if (wid < 2) {
            float bz0 = __ldg(gcb + o0), bz1 = __ldg(gcb + o1);
#pragma unroll
            for (int s = 0; s < 8; s++) {
                int t = s * 8 + 2 * tig;
                float2 r0 = { c2[s][0] + bz0, c2[s][1] + bz0 };
                float2 r1 = { c2[s][2] + bz1, c2[s][3] + bz1 };
                *(float2*)(g_y0 + obase + (size_t)o0 * 64 + t) = r0;
                *(float2*)(g_y0 + obase + (size_t)o1 * 64 + t) = r1;
            }
        } else if (wid < 4) {
            int z0 = o0 - 32, z1r = o1 - 32;
#pragma unroll
            for (int s = 0; s < 8; s++) {
                int t = s * 8 + 2 * tig;
                *(uint32_t*)(g_z1h + obase + (size_t)z0 * 64 + t) = bf16x2_of(c2[s][0], c2[s][1]);
                *(uint32_t*)(g_z1h + obase + (size_t)z1r * 64 + t) = bf16x2_of(c2[s][2], c2[s][3]);
            }
        } else {
            int z0 = o0 - 64, z1r = o1 - 64;
#pragma unroll
            for (int s = 0; s < 8; s++) {
                int t = s * 8 + 2 * tig;
                *(uint32_t*)(g_z2h + obase + (size_t)z0 * 64 + t) = bf16x2_of(c2[s][0], c2[s][1]);
                *(uint32_t*)(g_z2h + obase + (size_t)z1r * 64 + t) = bf16x2_of(c2[s][2], c2[s][3]);
            }
        }
    }
}

// ---------------- graph diffusion, bf16 MMA; 128x64 tile for 3+ blocks/SM ----------------
__global__ __launch_bounds__(256) void graph_mma(int layer) {
    __shared__ __align__(16) uint32_t Asp[2][16][136];
    __shared__ __align__(16) uint32_t Zsp[2][16][72];

    int tid = threadIdx.x;
    int m0 = blockIdx.x * 128;
    int n0 = blockIdx.y * 64;
    int bb = blockIdx.z;
    int lane = tid & 31, wid = tid >> 5;
    int wm = wid >> 1, wn = wid & 1;       // 4 m-tiles x 2 n-tiles
    int mbase = wm * 32, nbase = wn * 32;
    int g = lane >> 2, tig = lane & 3;

    int r = tid >> 4;              // kp row 0..15
    int seg = (tid & 15) * 8;      // A 8-word segment
    int segz = (tid & 15) * 4;     // Z 4-word segment

    float acc[2][4][4];
#pragma unroll
    for (int i = 0; i < 2; i++)
#pragma unroll
        for (int j = 0; j < 4; j++)
#pragma unroll
            for (int k = 0; k < 4; k++) acc[i][j][k] = 0.f;

    auto load_stage = [&](int st, int buf) {
        int e = st >> 4, s = st & 15;
        int kpg = s * 16 + r;
        const uint4* ap = (const uint4*)&g_Asp[e][kpg][m0 + seg];
        *(uint4*)&Asp[buf][r][seg]     = ap[0];
        *(uint4*)&Asp[buf][r][seg + 4] = ap[1];
        int v0 = 2 * kpg, v1 = v0 + 1;
        const __nv_bfloat16* zb = e ? g_z2h : g_z1h;
        size_t zoff = (size_t)bb * 1024000 + n0 + segz;
        uint2 lo = make_uint2(0, 0), hi = make_uint2(0, 0);
        if (v0 < 500) lo = *(const uint2*)(zb + zoff + (size_t)v0 * 2048);
        if (v1 < 500) hi = *(const uint2*)(zb + zoff + (size_t)v1 * 2048);
        uint4 o0;
        o0.x = __byte_perm(lo.x, hi.x, 0x5410); o0.y = __byte_perm(lo.x, hi.x, 0x7632);
        o0.z = __byte_perm(lo.y, hi.y, 0x5410); o0.w = __byte_perm(lo.y, hi.y, 0x7632);
        *(uint4*)&Zsp[buf][r][segz] = o0;
    };

    load_stage(0, 0);
    __syncthreads();

    for (int st = 0; st < 32; st++) {
        int cur = st & 1;
        if (st + 1 < 32) load_stage(st + 1, cur ^ 1);
#pragma unroll
        for (int ch = 0; ch < 2; ch++) {
            int k0 = ch * 8;
            uint32_t bfr[4][2];
#pragma unroll
            for (int nt = 0; nt < 4; nt++) {
                bfr[nt][0] = Zsp[cur][k0 + tig][nbase + nt * 8 + g];
                bfr[nt][1] = Zsp[cur][k0 + tig + 4][nbase + nt * 8 + g];
            }
#pragma unroll
            for (int mt = 0; mt < 2; mt++) {
                int mr = mbase + mt * 16 + g;
                uint32_t a0 = Asp[cur][k0 + tig][mr];
                uint32_t a1 = Asp[cur][k0 + tig][mr + 8];
                uint32_t a2 = Asp[cur][k0 + tig + 4][mr];
                uint32_t a3 = Asp[cur][k0 + tig + 4][mr + 8];
#pragma unroll
                for (int nt = 0; nt < 4; nt++)
                    mma_bf16(acc[mt][nt][0], acc[mt][nt][1], acc[mt][nt][2], acc[mt][nt][3],
                             a0, a1, a2, a3, bfr[nt][0], bfr[nt][1]);
            }
        }
        __syncthreads();
    }

    float* hout = g_h[layer];
    size_t bbase = (size_t)bb * 1024000;
    float s = 0.f, q = 0.f;
#pragma unroll
    for (int mt = 0; mt < 2; mt++) {
#pragma unroll
        for (int nt = 0; nt < 4; nt++) {
            int w0 = m0 + mbase + mt * 16 + g;
            int j = n0 + nbase + nt * 8 + 2 * tig;
            if (w0 < 500) {
                size_t idx = bbase + (size_t)w0 * 2048 + j;
                float2 y = *(const float2*)(g_y0 + idx);
                float2 rres;
                rres.x = acc[mt][nt][0] + y.x;
                rres.y = acc[mt][nt][1] + y.y;
                *(float2*)(hout + idx) = rres;
                s += rres.x + rres.y;
                q += rres.x * rres.x + rres.y * rres.y;
            }
            if (w0 + 8 < 500) {
                size_t idx = bbase + (size_t)(w0 + 8) * 2048 + j;
                float2 y = *(const float2*)(g_y0 + idx);
                float2 rres;
                rres.x = acc[mt][nt][2] + y.x;
                rres.y = acc[mt][nt][3] + y.y;
                *(float2*)(hout + idx) = rres;
                s += rres.x + rres.y;
                q += rres.x * rres.x + rres.y * rres.y;
            }
        }
    }
    for (int o = 16; o; o >>= 1) {
        s += __shfl_down_sync(0xffffffffu, s, o);
        q += __shfl_down_sync(0xffffffffu, q, o);
    }
    if (lane == 0) {
        int cw = (n0 + nbase) >> 6;    // 32-col warp span lies in one 64-col channel
        atomicAdd(&g_bnS[layer & 1][cw], s);
        atomicAdd(&g_bnQ[layer & 1][cw], q);
    }
}

// ---------------- fused attention: logits + softmax + weighted sum (round-9 design) ----------------
// dyn smem floats: vbuf[5][32][72] | e1s[64][72] | red[4][64] | lgs[5][64]  = 16704 fl
__global__ __launch_bounds__(256) void attn_fused(
    const float* __restrict__ x,
    const float* __restrict__ w1, const float* __restrict__ b1,
    const float* __restrict__ w2, const float* __restrict__ b2,
    const float* __restrict__ w3,
    float* __restrict__ out) {
    extern __shared__ float sm[];
    float* vbuf = sm;                // 5 x 2304 (32 rows x 72)
    float* e1s  = sm + 11520;        // 64 x 72
    float* red  = sm + 16128;        // 4 x 64
    float* lgs  = sm + 16384;        // 5 x 64

    int tid = threadIdx.x;
    int b = blockIdx.x / 500, n = blockIdx.x % 500;
    int lane = tid & 31, wid = tid >> 5;
    int wm = wid & 3;
    int wn = wid >> 2;
    int g = lane >> 2, tig = lane & 3;

    uint32_t a1f[4][4], a2f[8][4];
#pragma unroll
    for (int kk = 0; kk < 4; kk++) {
        a1f[kk][0] = tf32_bits(__ldg(w1 + (wm * 16 + g) * 32 + kk * 8 + tig));
        a1f[kk][1] = tf32_bits(__ldg(w1 + (wm * 16 + g + 8) * 32 + kk * 8 + tig));
        a1f[kk][2] = tf32_bits(__ldg(w1 + (wm * 16 + g) * 32 + kk * 8 + tig + 4));
        a1f[kk][3] = tf32_bits(__ldg(w1 + (wm * 16 + g + 8) * 32 + kk * 8 + tig + 4));
    }
#pragma unroll
    for (int kk = 0; kk < 8; kk++) {
        a2f[kk][0] = tf32_bits(__ldg(w2 + (wm * 16 + g) * 64 + kk * 8 + tig));
        a2f[kk][1] = tf32_bits(__ldg(w2 + (wm * 16 + g + 8) * 64 + kk * 8 + tig));
        a2f[kk][2] = tf32_bits(__ldg(w2 + (wm * 16 + g) * 64 + kk * 8 + tig + 4));
        a2f[kk][3] = tf32_bits(__ldg(w2 + (wm * 16 + g + 8) * 64 + kk * 8 + tig + 4));
    }
    float b1r0 = b1[wm * 16 + g], b1r1 = b1[wm * 16 + g + 8];
    float b2r0 = b2[wm * 16 + g], b2r1 = b2[wm * 16 + g + 8];
    float w3r0 = w3[wm * 16 + g], w3r1 = w3[wm * 16 + g + 8];

    for (int l = 0; l < 5; l++) {
        float* vb = vbuf + l * 2304;
        __syncthreads();
        if (l == 0) {
            const float* xb = x + (size_t)b * 1024000 + n * 64;
#pragma unroll
            for (int it = 0; it < 2; it++) {
                int i = tid + it * 256;
                int c = i >> 4, tq = (i & 15) * 4;
                float4 v = __ldg((const float4*)(xb + (size_t)c * 32000 + tq));
                float4 rv = { fmaxf(v.x, 0.f), fmaxf(v.y, 0.f), fmaxf(v.z, 0.f), fmaxf(v.w, 0.f) };
                *(float4*)&vb[c * 72 + tq] = rv;
            }
        } else {
            const float* hb = g_h[l - 1] + ((size_t)b * 500 + n) * 2048;
#pragma unroll
            for (int it = 0; it < 2; it++) {
                int i = tid + it * 256;
                int c = i >> 4, tq = (i & 15) * 4;
                float4 v = *(const float4*)(hb + i * 4);
                float4 rv = { fmaxf(v.x, 0.f), fmaxf(v.y, 0.f), fmaxf(v.z, 0.f), fmaxf(v.w, 0.f) };
                *(float4*)&vb[c * 72 + tq] = rv;
            }
        }
        __syncthreads();

        float c1[4][4];
#pragma unroll
        for (int sub = 0; sub < 4; sub++)
#pragma unroll
            for (int k = 0; k < 4; k++) c1[sub][k] = 0.f;
#pragma unroll
        for (int kk = 0; kk < 4; kk++) {
#pragma unroll
            for (int sub = 0; sub < 4; sub++) {
                int col = wn * 32 + sub * 8 + g;
                uint32_t bb0 = tf32_bits(vb[(kk * 8 + tig) * 72 + col]);
                uint32_t bb1 = tf32_bits(vb[(kk * 8 + tig + 4) * 72 + col]);
                mma_tf32(c1[sub][0], c1[sub][1], c1[sub][2], c1[sub][3],
                         a1f[kk][0], a1f[kk][1], a1f[kk][2], a1f[kk][3], bb0, bb1);
            }
        }
#pragma unroll
        for (int sub = 0; sub < 4; sub++) {
            int col = wn * 32 + sub * 8 + 2 * tig;
            e1s[(wm * 16 + g) * 72 + col]     = to_tf32(fmaxf(c1[sub][0] + b1r0, 0.f));
            e1s[(wm * 16 + g) * 72 + col + 1] = to_tf32(fmaxf(c1[sub][1] + b1r0, 0.f));
            e1s[(wm * 16 + g + 8) * 72 + col]     = to_tf32(fmaxf(c1[sub][2] + b1r1, 0.f));
            e1s[(wm * 16 + g + 8) * 72 + col + 1] = to_tf32(fmaxf(c1[sub][3] + b1r1, 0.f));
        }
        __syncthreads();

        float c2[4][4];
#pragma unroll
        for (int sub = 0; sub < 4; sub++)
#pragma unroll
            for (int k = 0; k < 4; k++) c2[sub][k] = 0.f;
#pragma unroll
        for (int kk = 0; kk < 8; kk++) {
#pragma unroll
            for (int sub = 0; sub < 4; sub++) {
                int col = wn * 32 + sub * 8 + g;
                uint32_t bb0 = __float_as_uint(e1s[(kk * 8 + tig) * 72 + col]);
                uint32_t bb1 = __float_as_uint(e1s[(kk * 8 + tig + 4) * 72 + col]);
                mma_tf32(c2[sub][0], c2[sub][1], c2[sub][2], c2[sub][3],
                         a2f[kk][0], a2f[kk][1], a2f[kk][2], a2f[kk][3], bb0, bb1);
            }
        }
        float p[4][2];
#pragma unroll
        for (int sub = 0; sub < 4; sub++) {
            p[sub][0] = w3r0 * fmaxf(c2[sub][0] + b2r0, 0.f) + w3r1 * fmaxf(c2[sub][2] + b2r1, 0.f);
            p[sub][1] = w3r0 * fmaxf(c2[sub][1] + b2r0, 0.f) + w3r1 * fmaxf(c2[sub][3] + b2r1, 0.f);
        }
#pragma unroll
        for (int off = 4; off <= 16; off <<= 1) {
#pragma unroll
            for (int sub = 0; sub < 4; sub++) {
                p[sub][0] += __shfl_xor_sync(0xffffffffu, p[sub][0], off);
                p[sub][1] += __shfl_xor_sync(0xffffffffu, p[sub][1], off);
            }
        }
        if (g == 0) {
#pragma unroll
            for (int sub = 0; sub < 4; sub++) {
                int col = wn * 32 + sub * 8 + 2 * tig;
                red[wm * 64 + col] = p[sub][0];
                red[wm * 64 + col + 1] = p[sub][1];
            }
        }
        __syncthreads();
        if (tid < 64)
            lgs[l * 64 + tid] = red[tid] + red[64 + tid] + red[128 + tid] + red[192 + tid];
    }
    __syncthreads();

    if (tid < 64) {
        float lg[5];
        float m = -1e30f;
#pragma unroll
        for (int l = 0; l < 5; l++) {
            lg[l] = lgs[l * 64 + tid];
            m = fmaxf(m, lg[l]);
        }
        float s = 0.f;
#pragma unroll
        for (int l = 0; l < 5; l++) { lg[l] = expf(lg[l] - m); s += lg[l]; }
        float inv = 1.f / s;
#pragma unroll
        for (int l = 0; l < 5; l++) lgs[l * 64 + tid] = lg[l] * inv;
    }
    __syncthreads();

    for (int i = tid; i < 2048; i += 256) {
        int c = i >> 6, t = i & 63;
        float s = lgs[t] * vbuf[c * 72 + t];
        s += lgs[64 + t]  * vbuf[2304 + c * 72 + t];
        s += lgs[128 + t] * vbuf[4608 + c * 72 + t];
        s += lgs[192 + t] * vbuf[6912 + c * 72 + t];
        s += lgs[256 + t] * vbuf[9216 + c * 72 + t];
        out[((size_t)(b * 32 + c) * 500 + n) * 64 + t] = s;
    }
}

// ---------------- launch ----------------
extern "C" void kernel_launch(void* const* d_in, const int* in_sizes, int n_in,
                              void* d_out, int out_size) {
    (void)in_sizes; (void)n_in; (void)out_size;
    const float* x        = (const float*)d_in[0];
    const float* supports = (const float*)d_in[1];
    const float* bn_gamma = (const float*)d_in[2];
    const float* bn_beta  = (const float*)d_in[3];
    const float* res_w    = (const float*)d_in[4];
    const float* res_b    = (const float*)d_in[5];
    const float* aff_w    = (const float*)d_in[6];
    const float* aff_b    = (const float*)d_in[7];
    const float* gate_w   = (const float*)d_in[8];
    const float* gate_b   = (const float*)d_in[9];
    const float* gc_w     = (const float*)d_in[10];
    const float* gc_b     = (const float*)d_in[11];
    const float* attn_w1  = (const float*)d_in[12];
    const float* attn_b1  = (const float*)d_in[13];
    const float* attn_w2  = (const float*)d_in[14];
    const float* attn_b2  = (const float*)d_in[15];
    const float* attn_w3  = (const float*)d_in[16];
    float* out = (float*)d_out;

    cudaFuncSetAttribute(attn_fused, cudaFuncAttributeMaxDynamicSharedMemorySize, 66816);

    prep_weights<<<64, 256>>>(res_w, aff_w, gate_w, gc_w, supports);
    bn_partial<<<dim3(32, 16), 256>>>(x);

    for (int l = 0; l < 4; l++) {
        st_front<<<8000, 256>>>(x, l, bn_gamma + l * 32, bn_beta + l * 32,
                                res_b + l * 32, aff_b + l * 32,
                                gate_b + l * 32, gc_b + l * 32);
        graph_mma<<<dim3(4, 32, 16), 256>>>(l);
    }
    attn_fused<<<8000, 256, 66816>>>(x, attn_w1, attn_b1, attn_w2, attn_b2, attn_w3, out);
}

// round 15
// speedup vs baseline: 1.4973x; 1.1882x over previous
#include <cuda_runtime.h>
#include <cuda_bf16.h>
#include <cstdint>

// ---------------- scratch (static __device__, no allocations) ----------------
// n-major activation layout: [b][n][c*64+t], b-stride 1,024,000
__device__ __align__(16) float g_h[4][16384000];
__device__ __align__(16) float g_y0[16384000];
// k-pair packed z: [b][kp][j] bf16x2 {z[2kp][j], z[2kp+1][j]}, kp padded to 256
__device__ __align__(16) uint32_t g_z1p[16 * 256 * 2048];
__device__ __align__(16) uint32_t g_z2p[16 * 256 * 2048];
__device__ __align__(16) uint32_t g_Asp[2][256][512];   // bf16x2 k-pair packed A, zero-padded
__device__ float g_bnsum[32 * 16], g_bnsq[32 * 16];     // layer-0 stats (from x)
__device__ float g_bnS[2][32], g_bnQ[2][32];            // ping-pong fused stats (layers >= 1)
// fragment-packed tf32 weights for st_front MMA
__device__ __align__(16) uint32_t g_w1f[4][4][16][128]; // [l][mt][kc][lane*4+reg]  (GEMM1 A)
__device__ __align__(16) uint32_t g_w2f[4][6][4][128];  // [l][mt2][kc][lane*4+reg] (GEMM2 A = W2, M=96)

// ---------------- helpers ----------------
__device__ __forceinline__ uint32_t bf16x2_of(float lo, float hi) {
    uint32_t r; asm("cvt.rn.bf16x2.f32 %0,%1,%2;" : "=r"(r) : "f"(hi), "f"(lo)); return r;
}
__device__ __forceinline__ float to_tf32(float x) {
    asm("cvt.rna.tf32.f32 %0, %1;" : "=f"(x) : "f"(x));
    return x;
}
__device__ __forceinline__ uint32_t tf32_bits(float x) { return __float_as_uint(to_tf32(x)); }

__device__ __forceinline__ void cp16(uint32_t smem_addr, const void* gptr) {
    asm volatile("cp.async.cg.shared.global [%0], [%1], 16;" :: "r"(smem_addr), "l"(gptr));
}
#define CP_COMMIT() asm volatile("cp.async.commit_group;")
#define CP_WAIT2()  asm volatile("cp.async.wait_group 2;")

__device__ __forceinline__ void mma_bf16(float& d0, float& d1, float& d2, float& d3,
                                         uint32_t a0, uint32_t a1, uint32_t a2, uint32_t a3,
                                         uint32_t b0, uint32_t b1) {
    asm volatile(
        "mma.sync.aligned.m16n8k16.row.col.f32.bf16.bf16.f32 "
        "{%0,%1,%2,%3},{%4,%5,%6,%7},{%8,%9},{%0,%1,%2,%3};"
        : "+f"(d0), "+f"(d1), "+f"(d2), "+f"(d3)
        : "r"(a0), "r"(a1), "r"(a2), "r"(a3), "r"(b0), "r"(b1));
}
__device__ __forceinline__ void mma_tf32(float& d0, float& d1, float& d2, float& d3,
                                         uint32_t a0, uint32_t a1, uint32_t a2, uint32_t a3,
                                         uint32_t b0, uint32_t b1) {
    asm volatile(
        "mma.sync.aligned.m16n8k8.row.col.f32.tf32.tf32.f32 "
        "{%0,%1,%2,%3},{%4,%5,%6,%7},{%8,%9},{%0,%1,%2,%3};"
        : "+f"(d0), "+f"(d1), "+f"(d2), "+f"(d3)
        : "r"(a0), "r"(a1), "r"(a2), "r"(a3), "r"(b0), "r"(b1));
}

// ---------------- weight packing ----------------
__global__ void prep_weights(const float* __restrict__ rw, const float* __restrict__ aw,
                             const float* __restrict__ gw, const float* __restrict__ gcw,
                             const float* __restrict__ A) {
    int tid = blockIdx.x * blockDim.x + threadIdx.x;
    int nt = gridDim.x * blockDim.x;

    // GEMM1 fragments. K order: k = 32*kk + c for conv taps kk=0..2; k = 96+c for res.
    for (int i = tid; i < 4 * 4 * 16 * 32; i += nt) {
        int l = i >> 11;
        int r = i & 2047;
        int mt = r >> 9;
        int r2 = r & 511;
        int kc = r2 >> 5;
        int lane = r2 & 31;
        int g = lane >> 2, tg = lane & 3;
        int o = mt * 8 + g;
        uint32_t* dst = &g_w1f[l][mt][kc][lane * 4];
#pragma unroll
        for (int half = 0; half < 2; half++) {
            int k = kc * 8 + tg + half * 4;
            int kk = k >> 5, c = k & 31;
            float va, vg;
            if (kk < 3) {
                va = aw[l * 3072 + o * 96 + c * 3 + kk];
                vg = gw[l * 3072 + o * 96 + c * 3 + kk];
            } else {
                va = rw[l * 1024 + o * 32 + c];
                vg = 0.f;
            }
            dst[half * 2 + 0] = tf32_bits(va);
            dst[half * 2 + 1] = tf32_bits(vg);
        }
    }
    // GEMM2 A fragments (W2, row-major M=96 x K=32)
    for (int i = tid; i < 4 * 6 * 4 * 32; i += nt) {
        int l = i / 768;
        int r = i % 768;
        int mt2 = r / 128;
        int r2 = r % 128;
        int kc = r2 >> 5;
        int lane = r2 & 31;
        int g = lane >> 2, tg = lane & 3;
        uint32_t* dst = &g_w2f[l][mt2][kc][lane * 4];
#pragma unroll
        for (int half = 0; half < 2; half++) {
            int k = kc * 8 + tg + half * 4;
#pragma unroll
            for (int rr = 0; rr < 2; rr++) {
                int o = mt2 * 16 + g + rr * 8;
                int grp = o >> 5, oo = o & 31;
                dst[half * 2 + rr] = tf32_bits(gcw[l * 3072 + oo * 96 + grp * 32 + k]);
            }
        }
    }
    // pack A supports into bf16x2 k-pairs
    for (int i = tid; i < 2 * 256 * 512; i += nt) {
        int e = i >> 17, kp = (i >> 9) & 255, m = i & 511;
        int v0 = 2 * kp, v1 = v0 + 1;
        float lo = (v0 < 500 && m < 500) ? A[(size_t)e * 250000 + (size_t)v0 * 500 + m] : 0.f;
        float hi = (v1 < 500 && m < 500) ? A[(size_t)e * 250000 + (size_t)v1 * 500 + m] : 0.f;
        g_Asp[e][kp][m] = bf16x2_of(lo, hi);
    }
    // zero z pad rows (kp = 250..255) once
    for (int i = tid; i < 2 * 16 * 6 * 2048; i += nt) {
        int e = i / (16 * 6 * 2048);
        int rem = i % (16 * 6 * 2048);
        int b = rem / (6 * 2048);
        int kp = 250 + (rem / 2048) % 6;
        int j = rem % 2048;
        uint32_t* dst = e ? g_z2p : g_z1p;
        dst[(size_t)b * 524288 + (size_t)kp * 2048 + j] = 0;
    }
}

// ---------------- batchnorm stats (input x only) ----------------
__global__ void bn_partial(const float* __restrict__ x) {
    int c = blockIdx.x, b = blockIdx.y;
    float s = 0.f, q = 0.f;
    const float* p = x + (size_t)(b * 32 + c) * 32000;
    for (int i = threadIdx.x; i < 8000; i += 256) {
        float4 v = __ldg((const float4*)(p + i * 4));
        s += v.x + v.y + v.z + v.w;
        q += v.x * v.x + v.y * v.y + v.z * v.z + v.w * v.w;
    }
    for (int o = 16; o; o >>= 1) {
        s += __shfl_down_sync(0xffffffffu, s, o);
        q += __shfl_down_sync(0xffffffffu, q, o);
    }
    __shared__ float ss[8], qq[8];
    int w = threadIdx.x >> 5;
    if ((threadIdx.x & 31) == 0) { ss[w] = s; qq[w] = q; }
    __syncthreads();
    if (threadIdx.x == 0) {
        float S = 0.f, Q = 0.f;
        for (int i = 0; i < 8; i++) { S += ss[i]; Q += qq[i]; }
        g_bnsum[c * 16 + b] = S;
        g_bnsq[c * 16 + b] = Q;
    }
}

// ---------------- st_front via tf32 tensor cores (bn finalize folded in) ----------------
__global__ __launch_bounds__(256) void st_front(
    const float* __restrict__ x, int layer,
    const float* __restrict__ gamma, const float* __restrict__ beta,
    const float* __restrict__ rb, const float* __restrict__ ab,
    const float* __restrict__ gb, const float* __restrict__ gcb) {
    __shared__ __align__(16) float ys[32][72];    // relu(bn(x)) at index t+2
    __shared__ __align__(16) float xs[32][72];    // raw x at index t+2
    __shared__ __align__(16) float x1C[32][72];   // x1: [c][t]
    __shared__ float s_scale[32], s_shift[32];

    int tid = threadIdx.x;
    int b = blockIdx.x / 500, n = blockIdx.x % 500;

    // bn finalize in-block
    if (tid < 32) {
        float S, Q;
        if (layer == 0) {
            S = 0.f; Q = 0.f;
#pragma unroll
            for (int bb2 = 0; bb2 < 16; bb2++) {
                S += g_bnsum[tid * 16 + bb2];
                Q += g_bnsq[tid * 16 + bb2];
            }
        } else {
            int pb = (layer - 1) & 1;
            S = g_bnS[pb][tid];
            Q = g_bnQ[pb][tid];
        }
        const float inv = 1.0f / 512000.0f;
        float m = S * inv;
        float var = Q * inv - m * m;
        float rstd = rsqrtf(var + 1e-5f);
        float sc = gamma[tid] * rstd;
        s_scale[tid] = sc;
        s_shift[tid] = beta[tid] - m * sc;
    }
    if (blockIdx.x == 0 && tid >= 32 && tid < 64) {
        g_bnS[layer & 1][tid - 32] = 0.f;
        g_bnQ[layer & 1][tid - 32] = 0.f;
    }
    if (tid < 64) ys[tid >> 1][tid & 1] = 0.f;   // left pads
    __syncthreads();

    if (layer == 0) {
        const float* xb = x + (size_t)b * 1024000 + n * 64;
#pragma unroll
        for (int it = 0; it < 2; it++) {
            int i = tid + it * 256;
            int c = i >> 4, tq = (i & 15) * 4;
            float4 v = __ldg((const float4*)(xb + (size_t)c * 32000 + tq));
            float sc = s_scale[c], sh = s_shift[c];
            float2 ya = { to_tf32(fmaxf(sc * v.x + sh, 0.f)), to_tf32(fmaxf(sc * v.y + sh, 0.f)) };
            float2 yb = { to_tf32(fmaxf(sc * v.z + sh, 0.f)), to_tf32(fmaxf(sc * v.w + sh, 0.f)) };
            *(float2*)&ys[c][tq + 2] = ya;
            *(float2*)&ys[c][tq + 4] = yb;
            float2 xa = { to_tf32(v.x), to_tf32(v.y) };
            float2 xb2 = { to_tf32(v.z), to_tf32(v.w) };
            *(float2*)&xs[c][tq + 2] = xa;
            *(float2*)&xs[c][tq + 4] = xb2;
        }
    } else {
        const float* hb = g_h[layer - 1] + ((size_t)b * 500 + n) * 2048;
#pragma unroll
        for (int it = 0; it < 2; it++) {
            int i = tid + it * 256;
            int c = i >> 4, tq = (i & 15) * 4;
            float4 v = *(const float4*)(hb + i * 4);
            float sc = s_scale[c], sh = s_shift[c];
            float2 ya = { to_tf32(fmaxf(sc * v.x + sh, 0.f)), to_tf32(fmaxf(sc * v.y + sh, 0.f)) };
            float2 yb = { to_tf32(fmaxf(sc * v.z + sh, 0.f)), to_tf32(fmaxf(sc * v.w + sh, 0.f)) };
            *(float2*)&ys[c][tq + 2] = ya;
            *(float2*)&ys[c][tq + 4] = yb;
            float2 xa = { to_tf32(v.x), to_tf32(v.y) };
            float2 xb2 = { to_tf32(v.z), to_tf32(v.w) };
            *(float2*)&xs[c][tq + 2] = xa;
            *(float2*)&xs[c][tq + 4] = xb2;
        }
    }
    __syncthreads();

    int lane = tid & 31, wid = tid >> 5;
    int g = lane >> 2, tig = lane & 3;
    int wm = wid & 3, wn = wid >> 2;
    int nbase = wn * 32;

    // ---- GEMM1 ----
    float c1[4][4];
#pragma unroll
    for (int s = 0; s < 4; s++)
#pragma unroll
        for (int k = 0; k < 4; k++) c1[s][k] = 0.f;

#pragma unroll
    for (int kc = 0; kc < 16; kc++) {
        uint4 af = __ldg((const uint4*)&g_w1f[layer][wm][kc][lane * 4]);
        int p = kc >> 2;
        int cb = (kc & 3) * 8;
        const float* base = (p < 3) ? &ys[cb][0] : &xs[cb][0];
        int off = (p < 3) ? p : 2;
#pragma unroll
        for (int s = 0; s < 4; s++) {
            int col = nbase + s * 8 + g + off;
            uint32_t b0 = __float_as_uint(base[tig * 72 + col]);
            uint32_t b1 = __float_as_uint(base[(tig + 4) * 72 + col]);
            mma_tf32(c1[s][0], c1[s][1], c1[s][2], c1[s][3],
                     af.x, af.y, af.z, af.w, b0, b1);
        }
    }

    // ---- x1 = tanh(aff+res+b) * sigmoid(gate+b); store as [c][t] ----
    {
        int o = wm * 8 + g;
        float abrb = __ldg(ab + o) + __ldg(rb + o);
        float gbv = __ldg(gb + o);
#pragma unroll
        for (int s = 0; s < 4; s++) {
            int col = nbase + s * 8 + 2 * tig;
            float v0 = tanhf(c1[s][0] + abrb) * (1.f / (1.f + expf(-(c1[s][2] + gbv))));
            float v1 = tanhf(c1[s][1] + abrb) * (1.f / (1.f + expf(-(c1[s][3] + gbv))));
            float2 pr = { to_tf32(v0), to_tf32(v1) };
            *(float2*)&x1C[o][col] = pr;
        }
    }
    __syncthreads();

    // ---- GEMM2: C[96 o][64 t] = W2 * x1C (warps 0..5) ----
    if (wid < 6) {
        float c2[8][4];
#pragma unroll
        for (int s = 0; s < 8; s++)
#pragma unroll
            for (int k = 0; k < 4; k++) c2[s][k] = 0.f;

#pragma unroll
        for (int kc = 0; kc < 4; kc++) {
            uint4 af = __ldg((const uint4*)&g_w2f[layer][wid][kc][lane * 4]);
#pragma unroll
            for (int s = 0; s < 8; s++) {
                int col = s * 8 + g;
                uint32_t b0 = __float_as_uint(x1C[kc * 8 + tig][col]);
                uint32_t b1 = __float_as_uint(x1C[kc * 8 + tig + 4][col]);
                mma_tf32(c2[s][0], c2[s][1], c2[s][2], c2[s][3],
                         af.x, af.y, af.z, af.w, b0, b1);
            }
        }

        int o0 = wid * 16 + g, o1 = o0 + 8;
        if (wid < 2) {
            size_t obase = ((size_t)b * 500 + n) * 2048;
            float bz0 = __ldg(gcb + o0), bz1 = __ldg(gcb + o1);
#pragma unroll
            for (int s = 0; s < 8; s++) {
                int t = s * 8 + 2 * tig;
                float2 r0 = { c2[s][0] + bz0, c2[s][1] + bz0 };
                float2 r1 = { c2[s][2] + bz1, c2[s][3] + bz1 };
                *(float2*)(g_y0 + obase + (size_t)o0 * 64 + t) = r0;
                *(float2*)(g_y0 + obase + (size_t)o1 * 64 + t) = r1;
            }
        } else {
            // z1 / z2 into k-pair packed layout: halfword (n&1) of word [b][n>>1][j]
            uint32_t* zw = (wid < 4) ? g_z1p : g_z2p;
            __nv_bfloat16* zp = (__nv_bfloat16*)zw;
            size_t zb2 = (((size_t)b * 256 + (n >> 1)) * 2048) * 2 + (n & 1);
            int z0 = (wid < 4) ? (o0 - 32) : (o0 - 64);
            int z1r = z0 + 8;
#pragma unroll
            for (int s = 0; s < 8; s++) {
                int t = s * 8 + 2 * tig;
                zp[zb2 + 2 * ((size_t)z0 * 64 + t)]       = __float2bfloat16(c2[s][0]);
                zp[zb2 + 2 * ((size_t)z0 * 64 + t + 1)]   = __float2bfloat16(c2[s][1]);
                zp[zb2 + 2 * ((size_t)z1r * 64 + t)]      = __float2bfloat16(c2[s][2]);
                zp[zb2 + 2 * ((size_t)z1r * 64 + t + 1)]  = __float2bfloat16(c2[s][3]);
            }
        }
    }
}

// ---------------- graph diffusion: bf16 MMA, 4-stage cp.async pipeline, 128x64 tile ----------------
__global__ __launch_bounds__(256) void graph_mma(int layer) {
    extern __shared__ uint32_t dsm[];
    uint32_t* As = dsm;            // 4 stages x [16][136]
    uint32_t* Zs = dsm + 8704;     // 4 stages x [16][72]

    int tid = threadIdx.x;
    int m0 = blockIdx.x * 128;
    int n0 = blockIdx.y * 64;
    int bb = blockIdx.z;
    int lane = tid & 31, wid = tid >> 5;
    int wm = wid >> 1, wn = wid & 1;       // 4 m-tiles x 2 n-tiles
    int mbase = wm * 32, nbase = wn * 32;
    int g = lane >> 2, tig = lane & 3;

    int r = tid >> 4;              // kp row 0..15
    int seg = (tid & 15) * 8;      // A 8-word segment
    int segz = (tid & 15) * 4;     // Z 4-word segment

    uint32_t smA = (uint32_t)__cvta_generic_to_shared(As);
    uint32_t smZ = (uint32_t)__cvta_generic_to_shared(Zs);

    float acc[2][4][4];
#pragma unroll
    for (int i = 0; i < 2; i++)
#pragma unroll
        for (int j = 0; j < 4; j++)
#pragma unroll
            for (int k = 0; k < 4; k++) acc[i][j][k] = 0.f;

    auto issue = [&](int st, int buf) {
        int e = st >> 4, s = st & 15;
        int kpg = s * 16 + r;
        const uint32_t* ap = &g_Asp[e][kpg][m0 + seg];
        uint32_t da = smA + (uint32_t)(buf * 2176 + r * 136 + seg) * 4;
        cp16(da, ap);
        cp16(da + 16, ap + 4);
        const uint32_t* zsrc = (e ? g_z2p : g_z1p)
                             + (size_t)bb * 524288 + (size_t)kpg * 2048 + n0 + segz;
        cp16(smZ + (uint32_t)(buf * 1152 + r * 72 + segz) * 4, zsrc);
    };

    issue(0, 0); CP_COMMIT();
    issue(1, 1); CP_COMMIT();
    issue(2, 2); CP_COMMIT();

    for (int st = 0; st < 32; st++) {
        CP_WAIT2();
        __syncthreads();
        int buf = st & 3;
        const uint32_t* Ab = As + buf * 2176;
        const uint32_t* Zb = Zs + buf * 1152;
#pragma unroll
        for (int ch = 0; ch < 2; ch++) {
            int k0 = ch * 8;
            uint32_t bfr[4][2];
#pragma unroll
            for (int nt = 0; nt < 4; nt++) {
                bfr[nt][0] = Zb[(k0 + tig) * 72 + nbase + nt * 8 + g];
                bfr[nt][1] = Zb[(k0 + tig + 4) * 72 + nbase + nt * 8 + g];
            }
#pragma unroll
            for (int mt = 0; mt < 2; mt++) {
                int mr = mbase + mt * 16 + g;
                uint32_t a0 = Ab[(k0 + tig) * 136 + mr];
                uint32_t a1 = Ab[(k0 + tig) * 136 + mr + 8];
                uint32_t a2 = Ab[(k0 + tig + 4) * 136 + mr];
                uint32_t a3 = Ab[(k0 + tig + 4) * 136 + mr + 8];
#pragma unroll
                for (int nt = 0; nt < 4; nt++)
                    mma_bf16(acc[mt][nt][0], acc[mt][nt][1], acc[mt][nt][2], acc[mt][nt][3],
                             a0, a1, a2, a3, bfr[nt][0], bfr[nt][1]);
            }
        }
        if (st + 3 < 32) issue(st + 3, (st + 3) & 3);
        CP_COMMIT();
    }

    float* hout = g_h[layer];
    size_t bbase = (size_t)bb * 1024000;
    float s = 0.f, q = 0.f;
#pragma unroll
    for (int mt = 0; mt < 2; mt++) {
#pragma unroll
        for (int nt = 0; nt < 4; nt++) {
            int w0 = m0 + mbase + mt * 16 + g;
            int j = n0 + nbase + nt * 8 + 2 * tig;
            if (w0 < 500) {
                size_t idx = bbase + (size_t)w0 * 2048 + j;
                float2 y = *(const float2*)(g_y0 + idx);
                float2 rres;
                rres.x = acc[mt][nt][0] + y.x;
                rres.y = acc[mt][nt][1] + y.y;
                *(float2*)(hout + idx) = rres;
                s += rres.x + rres.y;
                q += rres.x * rres.x + rres.y * rres.y;
            }
            if (w0 + 8 < 500) {
                size_t idx = bbase + (size_t)(w0 + 8) * 2048 + j;
                float2 y = *(const float2*)(g_y0 + idx);
                float2 rres;
                rres.x = acc[mt][nt][2] + y.x;
                rres.y = acc[mt][nt][3] + y.y;
                *(float2*)(hout + idx) = rres;
                s += rres.x + rres.y;
                q += rres.x * rres.x + rres.y * rres.y;
            }
        }
    }
    for (int o = 16; o; o >>= 1) {
        s += __shfl_down_sync(0xffffffffu, s, o);
        q += __shfl_down_sync(0xffffffffu, q, o);
    }
    if (lane == 0) {
        int cw = (n0 + nbase) >> 6;    // 32-col warp span lies in one 64-col channel
        atomicAdd(&g_bnS[layer & 1][cw], s);
        atomicAdd(&g_bnQ[layer & 1][cw], q);
    }
}

// ---------------- fused attention: logits + softmax + weighted sum (round-9 design) ----------------
// dyn smem floats: vbuf[5][32][72] | e1s[64][72] | red[4][64] | lgs[5][64]  = 16704 fl
__global__ __launch_bounds__(256) void attn_fused(
    const float* __restrict__ x,
    const float* __restrict__ w1, const float* __restrict__ b1,
    const float* __restrict__ w2, const float* __restrict__ b2,
    const float* __restrict__ w3,
    float* __restrict__ out) {
    extern __shared__ float sm[];
    float* vbuf = sm;                // 5 x 2304 (32 rows x 72)
    float* e1s  = sm + 11520;        // 64 x 72
    float* red  = sm + 16128;        // 4 x 64
    float* lgs  = sm + 16384;        // 5 x 64

    int tid = threadIdx.x;
    int b = blockIdx.x / 500, n = blockIdx.x % 500;
    int lane = tid & 31, wid = tid >> 5;
    int wm = wid & 3;
    int wn = wid >> 2;
    int g = lane >> 2, tig = lane & 3;

    uint32_t a1f[4][4], a2f[8][4];
#pragma unroll
    for (int kk = 0; kk < 4; kk++) {
        a1f[kk][0] = tf32_bits(__ldg(w1 + (wm * 16 + g) * 32 + kk * 8 + tig));
        a1f[kk][1] = tf32_bits(__ldg(w1 + (wm * 16 + g + 8) * 32 + kk * 8 + tig));
        a1f[kk][2] = tf32_bits(__ldg(w1 + (wm * 16 + g) * 32 + kk * 8 + tig + 4));
        a1f[kk][3] = tf32_bits(__ldg(w1 + (wm * 16 + g + 8) * 32 + kk * 8 + tig + 4));
    }
#pragma unroll
    for (int kk = 0; kk < 8; kk++) {
        a2f[kk][0] = tf32_bits(__ldg(w2 + (wm * 16 + g) * 64 + kk * 8 + tig));
        a2f[kk][1] = tf32_bits(__ldg(w2 + (wm * 16 + g + 8) * 64 + kk * 8 + tig));
        a2f[kk][2] = tf32_bits(__ldg(w2 + (wm * 16 + g) * 64 + kk * 8 + tig + 4));
        a2f[kk][3] = tf32_bits(__ldg(w2 + (wm * 16 + g + 8) * 64 + kk * 8 + tig + 4));
    }
    float b1r0 = b1[wm * 16 + g], b1r1 = b1[wm * 16 + g + 8];
    float b2r0 = b2[wm * 16 + g], b2r1 = b2[wm * 16 + g + 8];
    float w3r0 = w3[wm * 16 + g], w3r1 = w3[wm * 16 + g + 8];

    for (int l = 0; l < 5; l++) {
        float* vb = vbuf + l * 2304;
        __syncthreads();
        if (l == 0) {
            const float* xb = x + (size_t)b * 1024000 + n * 64;
#pragma unroll
            for (int it = 0; it < 2; it++) {
                int i = tid + it * 256;
                int c = i >> 4, tq = (i & 15) * 4;
                float4 v = __ldg((const float4*)(xb + (size_t)c * 32000 + tq));
                float4 rv = { fmaxf(v.x, 0.f), fmaxf(v.y, 0.f), fmaxf(v.z, 0.f), fmaxf(v.w, 0.f) };
                *(float4*)&vb[c * 72 + tq] = rv;
            }
        } else {
            const float* hb = g_h[l - 1] + ((size_t)b * 500 + n) * 2048;
#pragma unroll
            for (int it = 0; it < 2; it++) {
                int i = tid + it * 256;
                int c = i >> 4, tq = (i & 15) * 4;
                float4 v = *(const float4*)(hb + i * 4);
                float4 rv = { fmaxf(v.x, 0.f), fmaxf(v.y, 0.f), fmaxf(v.z, 0.f), fmaxf(v.w, 0.f) };
                *(float4*)&vb[c * 72 + tq] = rv;
            }
        }
        __syncthreads();

        float c1[4][4];
#pragma unroll
        for (int sub = 0; sub < 4; sub++)
#pragma unroll
            for (int k = 0; k < 4; k++) c1[sub][k] = 0.f;
#pragma unroll
        for (int kk = 0; kk < 4; kk++) {
#pragma unroll
            for (int sub = 0; sub < 4; sub++) {
                int col = wn * 32 + sub * 8 + g;
                uint32_t bb0 = tf32_bits(vb[(kk * 8 + tig) * 72 + col]);
                uint32_t bb1 = tf32_bits(vb[(kk * 8 + tig + 4) * 72 + col]);
                mma_tf32(c1[sub][0], c1[sub][1], c1[sub][2], c1[sub][3],
                         a1f[kk][0], a1f[kk][1], a1f[kk][2], a1f[kk][3], bb0, bb1);
            }
        }
#pragma unroll
        for (int sub = 0; sub < 4; sub++) {
            int col = wn * 32 + sub * 8 + 2 * tig;
            e1s[(wm * 16 + g) * 72 + col]     = to_tf32(fmaxf(c1[sub][0] + b1r0, 0.f));
            e1s[(wm * 16 + g) * 72 + col + 1] = to_tf32(fmaxf(c1[sub][1] + b1r0, 0.f));
            e1s[(wm * 16 + g + 8) * 72 + col]     = to_tf32(fmaxf(c1[sub][2] + b1r1, 0.f));
            e1s[(wm * 16 + g + 8) * 72 + col + 1] = to_tf32(fmaxf(c1[sub][3] + b1r1, 0.f));
        }
        __syncthreads();

        float c2[4][4];
#pragma unroll
        for (int sub = 0; sub < 4; sub++)
#pragma unroll
            for (int k = 0; k < 4; k++) c2[sub][k] = 0.f;
#pragma unroll
        for (int kk = 0; kk < 8; kk++) {
#pragma unroll
            for (int sub = 0; sub < 4; sub++) {
                int col = wn * 32 + sub * 8 + g;
                uint32_t bb0 = __float_as_uint(e1s[(kk * 8 + tig) * 72 + col]);
                uint32_t bb1 = __float_as_uint(e1s[(kk * 8 + tig + 4) * 72 + col]);
                mma_tf32(c2[sub][0], c2[sub][1], c2[sub][2], c2[sub][3],
                         a2f[kk][0], a2f[kk][1], a2f[kk][2], a2f[kk][3], bb0, bb1);
            }
        }
        float p[4][2];
#pragma unroll
        for (int sub = 0; sub < 4; sub++) {
            p[sub][0] = w3r0 * fmaxf(c2[sub][0] + b2r0, 0.f) + w3r1 * fmaxf(c2[sub][2] + b2r1, 0.f);
            p[sub][1] = w3r0 * fmaxf(c2[sub][1] + b2r0, 0.f) + w3r1 * fmaxf(c2[sub][3] + b2r1, 0.f);
        }
#pragma unroll
        for (int off = 4; off <= 16; off <<= 1) {
#pragma unroll
            for (int sub = 0; sub < 4; sub++) {
                p[sub][0] += __shfl_xor_sync(0xffffffffu, p[sub][0], off);
                p[sub][1] += __shfl_xor_sync(0xffffffffu, p[sub][1], off);
            }
        }
        if (g == 0) {
#pragma unroll
            for (int sub = 0; sub < 4; sub++) {
                int col = wn * 32 + sub * 8 + 2 * tig;
                red[wm * 64 + col] = p[sub][0];
                red[wm * 64 + col + 1] = p[sub][1];
            }
        }
        __syncthreads();
        if (tid < 64)
            lgs[l * 64 + tid] = red[tid] + red[64 + tid] + red[128 + tid] + red[192 + tid];
    }
    __syncthreads();

    if (tid < 64) {
        float lg[5];
        float m = -1e30f;
#pragma unroll
        for (int l = 0; l < 5; l++) {
            lg[l] = lgs[l * 64 + tid];
            m = fmaxf(m, lg[l]);
        }
        float s = 0.f;
#pragma unroll
        for (int l = 0; l < 5; l++) { lg[l] = expf(lg[l] - m); s += lg[l]; }
        float inv = 1.f / s;
#pragma unroll
        for (int l = 0; l < 5; l++) lgs[l * 64 + tid] = lg[l] * inv;
    }
    __syncthreads();

    for (int i = tid; i < 2048; i += 256) {
        int c = i >> 6, t = i & 63;
        float s = lgs[t] * vbuf[c * 72 + t];
        s += lgs[64 + t]  * vbuf[2304 + c * 72 + t];
        s += lgs[128 + t] * vbuf[4608 + c * 72 + t];
        s += lgs[192 + t] * vbuf[6912 + c * 72 + t];
        s += lgs[256 + t] * vbuf[9216 + c * 72 + t];
        out[((size_t)(b * 32 + c) * 500 + n) * 64 + t] = s;
    }
}

// ---------------- launch ----------------
extern "C" void kernel_launch(void* const* d_in, const int* in_sizes, int n_in,
                              void* d_out, int out_size) {
    (void)in_sizes; (void)n_in; (void)out_size;
    const float* x        = (const float*)d_in[0];
    const float* supports = (const float*)d_in[1];
    const float* bn_gamma = (const float*)d_in[2];
    const float* bn_beta  = (const float*)d_in[3];
    const float* res_w    = (const float*)d_in[4];
    const float* res_b    = (const float*)d_in[5];
    const float* aff_w    = (const float*)d_in[6];
    const float* aff_b    = (const float*)d_in[7];
    const float* gate_w   = (const float*)d_in[8];
    const float* gate_b   = (const float*)d_in[9];
    const float* gc_w     = (const float*)d_in[10];
    const float* gc_b     = (const float*)d_in[11];
    const float* attn_w1  = (const float*)d_in[12];
    const float* attn_b1  = (const float*)d_in[13];
    const float* attn_w2  = (const float*)d_in[14];
    const float* attn_b2  = (const float*)d_in[15];
    const float* attn_w3  = (const float*)d_in[16];
    float* out = (float*)d_out;

    cudaFuncSetAttribute(attn_fused, cudaFuncAttributeMaxDynamicSharedMemorySize, 66816);
    cudaFuncSetAttribute(graph_mma, cudaFuncAttributeMaxDynamicSharedMemorySize, 53248);

    prep_weights<<<64, 256>>>(res_w, aff_w, gate_w, gc_w, supports);
    bn_partial<<<dim3(32, 16), 256>>>(x);

    for (int l = 0; l < 4; l++) {
        st_front<<<8000, 256>>>(x, l, bn_gamma + l * 32, bn_beta + l * 32,
                                res_b + l * 32, aff_b + l * 32,
                                gate_b + l * 32, gc_b + l * 32);
        graph_mma<<<dim3(4, 32, 16), 256, 53248>>>(l);
    }
    attn_fused<<<8000, 256, 66816>>>(x, attn_w1, attn_b1, attn_w2, attn_b2, attn_w3, out);
}

// round 16
// speedup vs baseline: 1.5457x; 1.0323x over previous
#include <cuda_runtime.h>
#include <cuda_bf16.h>
#include <cstdint>

// ---------------- scratch (static __device__, no allocations) ----------------
// n-major activation layout: [b][n][c*64+t], b-stride 1,024,000
__device__ __align__(16) float g_h[4][16384000];
__device__ __align__(16) float g_y0[16384000];
// k-pair packed z: [b][kp][j] bf16x2 {z[2kp][j], z[2kp+1][j]}, kp padded to 256
__device__ __align__(16) uint32_t g_z1p[16 * 256 * 2048];
__device__ __align__(16) uint32_t g_z2p[16 * 256 * 2048];
__device__ __align__(16) uint32_t g_Asp[2][256][512];   // bf16x2 k-pair packed A, zero-padded
__device__ float g_bnsum[32 * 16], g_bnsq[32 * 16];     // layer-0 stats (from x)
__device__ float g_bnS[2][32], g_bnQ[2][32];            // ping-pong fused stats (layers >= 1)
// fragment-packed tf32 weights for st_front MMA
__device__ __align__(16) uint32_t g_w1f[4][4][16][128]; // [l][mt][kc][lane*4+reg]  (GEMM1 A)
__device__ __align__(16) uint32_t g_w2f[4][6][4][128];  // [l][mt2][kc][lane*4+reg] (GEMM2 A = W2, M=96)

// ---------------- helpers ----------------
__device__ __forceinline__ uint32_t bf16x2_of(float lo, float hi) {
    uint32_t r; asm("cvt.rn.bf16x2.f32 %0,%1,%2;" : "=r"(r) : "f"(hi), "f"(lo)); return r;
}
__device__ __forceinline__ float to_tf32(float x) {
    asm("cvt.rna.tf32.f32 %0, %1;" : "=f"(x) : "f"(x));
    return x;
}
__device__ __forceinline__ uint32_t tf32_bits(float x) { return __float_as_uint(to_tf32(x)); }

__device__ __forceinline__ void cp16(uint32_t smem_addr, const void* gptr) {
    asm volatile("cp.async.cg.shared.global [%0], [%1], 16;" :: "r"(smem_addr), "l"(gptr));
}
#define CP_COMMIT() asm volatile("cp.async.commit_group;")
#define CP_WAIT2()  asm volatile("cp.async.wait_group 2;")

__device__ __forceinline__ void mma_bf16(float& d0, float& d1, float& d2, float& d3,
                                         uint32_t a0, uint32_t a1, uint32_t a2, uint32_t a3,
                                         uint32_t b0, uint32_t b1) {
    asm volatile(
        "mma.sync.aligned.m16n8k16.row.col.f32.bf16.bf16.f32 "
        "{%0,%1,%2,%3},{%4,%5,%6,%7},{%8,%9},{%0,%1,%2,%3};"
        : "+f"(d0), "+f"(d1), "+f"(d2), "+f"(d3)
        : "r"(a0), "r"(a1), "r"(a2), "r"(a3), "r"(b0), "r"(b1));
}
__device__ __forceinline__ void mma_tf32(float& d0, float& d1, float& d2, float& d3,
                                         uint32_t a0, uint32_t a1, uint32_t a2, uint32_t a3,
                                         uint32_t b0, uint32_t b1) {
    asm volatile(
        "mma.sync.aligned.m16n8k8.row.col.f32.tf32.tf32.f32 "
        "{%0,%1,%2,%3},{%4,%5,%6,%7},{%8,%9},{%0,%1,%2,%3};"
        : "+f"(d0), "+f"(d1), "+f"(d2), "+f"(d3)
        : "r"(a0), "r"(a1), "r"(a2), "r"(a3), "r"(b0), "r"(b1));
}

// ---------------- weight packing ----------------
__global__ void prep_weights(const float* __restrict__ rw, const float* __restrict__ aw,
                             const float* __restrict__ gw, const float* __restrict__ gcw,
                             const float* __restrict__ A) {
    int tid = blockIdx.x * blockDim.x + threadIdx.x;
    int nt = gridDim.x * blockDim.x;

    // GEMM1 fragments. K order: k = 32*kk + c for conv taps kk=0..2; k = 96+c for res.
    for (int i = tid; i < 4 * 4 * 16 * 32; i += nt) {
        int l = i >> 11;
        int r = i & 2047;
        int mt = r >> 9;
        int r2 = r & 511;
        int kc = r2 >> 5;
        int lane = r2 & 31;
        int g = lane >> 2, tg = lane & 3;
        int o = mt * 8 + g;
        uint32_t* dst = &g_w1f[l][mt][kc][lane * 4];
#pragma unroll
        for (int half = 0; half < 2; half++) {
            int k = kc * 8 + tg + half * 4;
            int kk = k >> 5, c = k & 31;
            float va, vg;
            if (kk < 3) {
                va = aw[l * 3072 + o * 96 + c * 3 + kk];
                vg = gw[l * 3072 + o * 96 + c * 3 + kk];
            } else {
                va = rw[l * 1024 + o * 32 + c];
                vg = 0.f;
            }
            dst[half * 2 + 0] = tf32_bits(va);
            dst[half * 2 + 1] = tf32_bits(vg);
        }
    }
    // GEMM2 A fragments (W2, row-major M=96 x K=32)
    for (int i = tid; i < 4 * 6 * 4 * 32; i += nt) {
        int l = i / 768;
        int r = i % 768;
        int mt2 = r / 128;
        int r2 = r % 128;
        int kc = r2 >> 5;
        int lane = r2 & 31;
        int g = lane >> 2, tg = lane & 3;
        uint32_t* dst = &g_w2f[l][mt2][kc][lane * 4];
#pragma unroll
        for (int half = 0; half < 2; half++) {
            int k = kc * 8 + tg + half * 4;
#pragma unroll
            for (int rr = 0; rr < 2; rr++) {
                int o = mt2 * 16 + g + rr * 8;
                int grp = o >> 5, oo = o & 31;
                dst[half * 2 + rr] = tf32_bits(gcw[l * 3072 + oo * 96 + grp * 32 + k]);
            }
        }
    }
    // pack A supports into bf16x2 k-pairs
    for (int i = tid; i < 2 * 256 * 512; i += nt) {
        int e = i >> 17, kp = (i >> 9) & 255, m = i & 511;
        int v0 = 2 * kp, v1 = v0 + 1;
        float lo = (v0 < 500 && m < 500) ? A[(size_t)e * 250000 + (size_t)v0 * 500 + m] : 0.f;
        float hi = (v1 < 500 && m < 500) ? A[(size_t)e * 250000 + (size_t)v1 * 500 + m] : 0.f;
        g_Asp[e][kp][m] = bf16x2_of(lo, hi);
    }
    // zero z pad rows (kp = 250..255) once
    for (int i = tid; i < 2 * 16 * 6 * 2048; i += nt) {
        int e = i / (16 * 6 * 2048);
        int rem = i % (16 * 6 * 2048);
        int b = rem / (6 * 2048);
        int kp = 250 + (rem / 2048) % 6;
        int j = rem % 2048;
        uint32_t* dst = e ? g_z2p : g_z1p;
        dst[(size_t)b * 524288 + (size_t)kp * 2048 + j] = 0;
    }
}

// ---------------- batchnorm stats (input x only) ----------------
__global__ void bn_partial(const float* __restrict__ x) {
    int c = blockIdx.x, b = blockIdx.y;
    float s = 0.f, q = 0.f;
    const float* p = x + (size_t)(b * 32 + c) * 32000;
    for (int i = threadIdx.x; i < 8000; i += 256) {
        float4 v = __ldg((const float4*)(p + i * 4));
        s += v.x + v.y + v.z + v.w;
        q += v.x * v.x + v.y * v.y + v.z * v.z + v.w * v.w;
    }
    for (int o = 16; o; o >>= 1) {
        s += __shfl_down_sync(0xffffffffu, s, o);
        q += __shfl_down_sync(0xffffffffu, q, o);
    }
    __shared__ float ss[8], qq[8];
    int w = threadIdx.x >> 5;
    if ((threadIdx.x & 31) == 0) { ss[w] = s; qq[w] = q; }
    __syncthreads();
    if (threadIdx.x == 0) {
        float S = 0.f, Q = 0.f;
        for (int i = 0; i < 8; i++) { S += ss[i]; Q += qq[i]; }
        g_bnsum[c * 16 + b] = S;
        g_bnsq[c * 16 + b] = Q;
    }
}

// ---------------- st_front via tf32 tensor cores (bn finalize folded in) ----------------
__global__ __launch_bounds__(256) void st_front(
    const float* __restrict__ x, int layer,
    const float* __restrict__ gamma, const float* __restrict__ beta,
    const float* __restrict__ rb, const float* __restrict__ ab,
    const float* __restrict__ gb, const float* __restrict__ gcb) {
    __shared__ __align__(16) float ys[32][72];    // relu(bn(x)) at index t+2
    __shared__ __align__(16) float xs[32][72];    // raw x at index t+2
    __shared__ __align__(16) float x1C[32][72];   // x1: [c][t]
    __shared__ float s_scale[32], s_shift[32];

    int tid = threadIdx.x;
    int b = blockIdx.x / 500, n = blockIdx.x % 500;

    // bn finalize in-block
    if (tid < 32) {
        float S, Q;
        if (layer == 0) {
            S = 0.f; Q = 0.f;
#pragma unroll
            for (int bb2 = 0; bb2 < 16; bb2++) {
                S += g_bnsum[tid * 16 + bb2];
                Q += g_bnsq[tid * 16 + bb2];
            }
        } else {
            int pb = (layer - 1) & 1;
            S = g_bnS[pb][tid];
            Q = g_bnQ[pb][tid];
        }
        const float inv = 1.0f / 512000.0f;
        float m = S * inv;
        float var = Q * inv - m * m;
        float rstd = rsqrtf(var + 1e-5f);
        float sc = gamma[tid] * rstd;
        s_scale[tid] = sc;
        s_shift[tid] = beta[tid] - m * sc;
    }
    if (blockIdx.x == 0 && tid >= 32 && tid < 64) {
        g_bnS[layer & 1][tid - 32] = 0.f;
        g_bnQ[layer & 1][tid - 32] = 0.f;
    }
    if (tid < 64) ys[tid >> 1][tid & 1] = 0.f;   // left pads
    __syncthreads();

    if (layer == 0) {
        const float* xb = x + (size_t)b * 1024000 + n * 64;
#pragma unroll
        for (int it = 0; it < 2; it++) {
            int i = tid + it * 256;
            int c = i >> 4, tq = (i & 15) * 4;
            float4 v = __ldg((const float4*)(xb + (size_t)c * 32000 + tq));
            float sc = s_scale[c], sh = s_shift[c];
            float2 ya = { to_tf32(fmaxf(sc * v.x + sh, 0.f)), to_tf32(fmaxf(sc * v.y + sh, 0.f)) };
            float2 yb = { to_tf32(fmaxf(sc * v.z + sh, 0.f)), to_tf32(fmaxf(sc * v.w + sh, 0.f)) };
            *(float2*)&ys[c][tq + 2] = ya;
            *(float2*)&ys[c][tq + 4] = yb;
            float2 xa = { to_tf32(v.x), to_tf32(v.y) };
            float2 xb2 = { to_tf32(v.z), to_tf32(v.w) };
            *(float2*)&xs[c][tq + 2] = xa;
            *(float2*)&xs[c][tq + 4] = xb2;
        }
    } else {
        const float* hb = g_h[layer - 1] + ((size_t)b * 500 + n) * 2048;
#pragma unroll
        for (int it = 0; it < 2; it++) {
            int i = tid + it * 256;
            int c = i >> 4, tq = (i & 15) * 4;
            float4 v = *(const float4*)(hb + i * 4);
            float sc = s_scale[c], sh = s_shift[c];
            float2 ya = { to_tf32(fmaxf(sc * v.x + sh, 0.f)), to_tf32(fmaxf(sc * v.y + sh, 0.f)) };
            float2 yb = { to_tf32(fmaxf(sc * v.z + sh, 0.f)), to_tf32(fmaxf(sc * v.w + sh, 0.f)) };
            *(float2*)&ys[c][tq + 2] = ya;
            *(float2*)&ys[c][tq + 4] = yb;
            float2 xa = { to_tf32(v.x), to_tf32(v.y) };
            float2 xb2 = { to_tf32(v.z), to_tf32(v.w) };
            *(float2*)&xs[c][tq + 2] = xa;
            *(float2*)&xs[c][tq + 4] = xb2;
        }
    }
    __syncthreads();

    int lane = tid & 31, wid = tid >> 5;
    int g = lane >> 2, tig = lane & 3;
    int wm = wid & 3, wn = wid >> 2;
    int nbase = wn * 32;

    // ---- GEMM1 ----
    float c1[4][4];
#pragma unroll
    for (int s = 0; s < 4; s++)
#pragma unroll
        for (int k = 0; k < 4; k++) c1[s][k] = 0.f;

#pragma unroll
    for (int kc = 0; kc < 16; kc++) {
        uint4 af = __ldg((const uint4*)&g_w1f[layer][wm][kc][lane * 4]);
        int p = kc >> 2;
        int cb = (kc & 3) * 8;
        const float* base = (p < 3) ? &ys[cb][0] : &xs[cb][0];
        int off = (p < 3) ? p : 2;
#pragma unroll
        for (int s = 0; s < 4; s++) {
            int col = nbase + s * 8 + g + off;
            uint32_t b0 = __float_as_uint(base[tig * 72 + col]);
            uint32_t b1 = __float_as_uint(base[(tig + 4) * 72 + col]);
            mma_tf32(c1[s][0], c1[s][1], c1[s][2], c1[s][3],
                     af.x, af.y, af.z, af.w, b0, b1);
        }
    }

    // ---- x1 = tanh(aff+res+b) * sigmoid(gate+b); store as [c][t] ----
    {
        int o = wm * 8 + g;
        float abrb = __ldg(ab + o) + __ldg(rb + o);
        float gbv = __ldg(gb + o);
#pragma unroll
        for (int s = 0; s < 4; s++) {
            int col = nbase + s * 8 + 2 * tig;
            float v0 = tanhf(c1[s][0] + abrb) * (1.f / (1.f + expf(-(c1[s][2] + gbv))));
            float v1 = tanhf(c1[s][1] + abrb) * (1.f / (1.f + expf(-(c1[s][3] + gbv))));
            float2 pr = { to_tf32(v0), to_tf32(v1) };
            *(float2*)&x1C[o][col] = pr;
        }
    }
    __syncthreads();

    // ---- GEMM2: C[96 o][64 t] = W2 * x1C (warps 0..5) ----
    if (wid < 6) {
        float c2[8][4];
#pragma unroll
        for (int s = 0; s < 8; s++)
#pragma unroll
            for (int k = 0; k < 4; k++) c2[s][k] = 0.f;

#pragma unroll
        for (int kc = 0; kc < 4; kc++) {
            uint4 af = __ldg((const uint4*)&g_w2f[layer][wid][kc][lane * 4]);
#pragma unroll
            for (int s = 0; s < 8; s++) {
                int col = s * 8 + g;
                uint32_t b0 = __float_as_uint(x1C[kc * 8 + tig][col]);
                uint32_t b1 = __float_as_uint(x1C[kc * 8 + tig + 4][col]);
                mma_tf32(c2[s][0], c2[s][1], c2[s][2], c2[s][3],
                         af.x, af.y, af.z, af.w, b0, b1);
            }
        }

        int o0 = wid * 16 + g, o1 = o0 + 8;
        if (wid < 2) {
            size_t obase = ((size_t)b * 500 + n) * 2048;
            float bz0 = __ldg(gcb + o0), bz1 = __ldg(gcb + o1);
#pragma unroll
            for (int s = 0; s < 8; s++) {
                int t = s * 8 + 2 * tig;
                float2 r0 = { c2[s][0] + bz0, c2[s][1] + bz0 };
                float2 r1 = { c2[s][2] + bz1, c2[s][3] + bz1 };
                *(float2*)(g_y0 + obase + (size_t)o0 * 64 + t) = r0;
                *(float2*)(g_y0 + obase + (size_t)o1 * 64 + t) = r1;
            }
        } else {
            // z1 / z2 into k-pair packed layout: halfword (n&1) of word [b][n>>1][j]
            uint32_t* zw = (wid < 4) ? g_z1p : g_z2p;
            __nv_bfloat16* zp = (__nv_bfloat16*)zw;
            size_t zb2 = (((size_t)b * 256 + (n >> 1)) * 2048) * 2 + (n & 1);
            int z0 = (wid < 4) ? (o0 - 32) : (o0 - 64);
            int z1r = z0 + 8;
#pragma unroll
            for (int s = 0; s < 8; s++) {
                int t = s * 8 + 2 * tig;
                zp[zb2 + 2 * ((size_t)z0 * 64 + t)]       = __float2bfloat16(c2[s][0]);
                zp[zb2 + 2 * ((size_t)z0 * 64 + t + 1)]   = __float2bfloat16(c2[s][1]);
                zp[zb2 + 2 * ((size_t)z1r * 64 + t)]      = __float2bfloat16(c2[s][2]);
                zp[zb2 + 2 * ((size_t)z1r * 64 + t + 1)]  = __float2bfloat16(c2[s][3]);
            }
        }
    }
}

// ---------------- graph diffusion: bf16 MMA, 4-stage cp.async pipeline, 128x64 tile ----------------
__global__ __launch_bounds__(256) void graph_mma(int layer) {
    extern __shared__ uint32_t dsm[];
    uint32_t* As = dsm;            // 4 stages x [16][136]
    uint32_t* Zs = dsm + 8704;     // 4 stages x [16][72]

    int tid = threadIdx.x;
    int m0 = blockIdx.x * 128;
    int n0 = blockIdx.y * 64;
    int bb = blockIdx.z;
    int lane = tid & 31, wid = tid >> 5;
    int wm = wid >> 1, wn = wid & 1;       // 4 m-tiles x 2 n-tiles
    int mbase = wm * 32, nbase = wn * 32;
    int g = lane >> 2, tig = lane & 3;

    int r = tid >> 4;              // kp row 0..15
    int seg = (tid & 15) * 8;      // A 8-word segment
    int segz = (tid & 15) * 4;     // Z 4-word segment

    uint32_t smA = (uint32_t)__cvta_generic_to_shared(As);
    uint32_t smZ = (uint32_t)__cvta_generic_to_shared(Zs);

    float acc[2][4][4];
#pragma unroll
    for (int i = 0; i < 2; i++)
#pragma unroll
        for (int j = 0; j < 4; j++)
#pragma unroll
            for (int k = 0; k < 4; k++) acc[i][j][k] = 0.f;

    auto issue = [&](int st, int buf) {
        int e = st >> 4, s = st & 15;
        int kpg = s * 16 + r;
        const uint32_t* ap = &g_Asp[e][kpg][m0 + seg];
        uint32_t da = smA + (uint32_t)(buf * 2176 + r * 136 + seg) * 4;
        cp16(da, ap);
        cp16(da + 16, ap + 4);
        const uint32_t* zsrc = (e ? g_z2p : g_z1p)
                             + (size_t)bb * 524288 + (size_t)kpg * 2048 + n0 + segz;
        cp16(smZ + (uint32_t)(buf * 1152 + r * 72 + segz) * 4, zsrc);
    };

    issue(0, 0); CP_COMMIT();
    issue(1, 1); CP_COMMIT();
    issue(2, 2); CP_COMMIT();

    for (int st = 0; st < 32; st++) {
        CP_WAIT2();
        __syncthreads();
        int buf = st & 3;
        const uint32_t* Ab = As + buf * 2176;
        const uint32_t* Zb = Zs + buf * 1152;
#pragma unroll
        for (int ch = 0; ch < 2; ch++) {
            int k0 = ch * 8;
            uint32_t bfr[4][2];
#pragma unroll
            for (int nt = 0; nt < 4; nt++) {
                bfr[nt][0] = Zb[(k0 + tig) * 72 + nbase + nt * 8 + g];
                bfr[nt][1] = Zb[(k0 + tig + 4) * 72 + nbase + nt * 8 + g];
            }
#pragma unroll
            for (int mt = 0; mt < 2; mt++) {
                int mr = mbase + mt * 16 + g;
                uint32_t a0 = Ab[(k0 + tig) * 136 + mr];
                uint32_t a1 = Ab[(k0 + tig) * 136 + mr + 8];
                uint32_t a2 = Ab[(k0 + tig + 4) * 136 + mr];
                uint32_t a3 = Ab[(k0 + tig + 4) * 136 + mr + 8];
#pragma unroll
                for (int nt = 0; nt < 4; nt++)
                    mma_bf16(acc[mt][nt][0], acc[mt][nt][1], acc[mt][nt][2], acc[mt][nt][3],
                             a0, a1, a2, a3, bfr[nt][0], bfr[nt][1]);
            }
        }
        if (st + 3 < 32) issue(st + 3, (st + 3) & 3);
        CP_COMMIT();
    }

    float* hout = g_h[layer];
    size_t bbase = (size_t)bb * 1024000;
    float s = 0.f, q = 0.f;
#pragma unroll
    for (int mt = 0; mt < 2; mt++) {
#pragma unroll
        for (int nt = 0; nt < 4; nt++) {
            int w0 = m0 + mbase + mt * 16 + g;
            int j = n0 + nbase + nt * 8 + 2 * tig;
            if (w0 < 500) {
                size_t idx = bbase + (size_t)w0 * 2048 + j;
                float2 y = *(const float2*)(g_y0 + idx);
                float2 rres;
                rres.x = acc[mt][nt][0] + y.x;
                rres.y = acc[mt][nt][1] + y.y;
                *(float2*)(hout + idx) = rres;
                s += rres.x + rres.y;
                q += rres.x * rres.x + rres.y * rres.y;
            }
            if (w0 + 8 < 500) {
                size_t idx = bbase + (size_t)(w0 + 8) * 2048 + j;
                float2 y = *(const float2*)(g_y0 + idx);
                float2 rres;
                rres.x = acc[mt][nt][2] + y.x;
                rres.y = acc[mt][nt][3] + y.y;
                *(float2*)(hout + idx) = rres;
                s += rres.x + rres.y;
                q += rres.x * rres.x + rres.y * rres.y;
            }
        }
    }
    for (int o = 16; o; o >>= 1) {
        s += __shfl_down_sync(0xffffffffu, s, o);
        q += __shfl_down_sync(0xffffffffu, q, o);
    }
    if (lane == 0) {
        int cw = (n0 + nbase) >> 6;    // 32-col warp span lies in one 64-col channel
        atomicAdd(&g_bnS[layer & 1][cw], s);
        atomicAdd(&g_bnQ[layer & 1][cw], q);
    }
}

// ---------------- fused attention with cp.async cross-layer prefetch ----------------
// dyn smem floats: vbuf[5][32][72] (RAW h/x) | e1s[64][72] | red[4][64] | lgs[5][64] = 16704 fl
__global__ __launch_bounds__(256) void attn_fused(
    const float* __restrict__ x,
    const float* __restrict__ w1, const float* __restrict__ b1,
    const float* __restrict__ w2, const float* __restrict__ b2,
    const float* __restrict__ w3,
    float* __restrict__ out) {
    extern __shared__ float sm[];
    float* vbuf = sm;                // 5 x 2304 (raw values; relu applied at read)
    float* e1s  = sm + 11520;        // 64 x 72
    float* red  = sm + 16128;        // 4 x 64
    float* lgs  = sm + 16384;        // 5 x 64

    int tid = threadIdx.x;
    int b = blockIdx.x / 500, n = blockIdx.x % 500;
    int lane = tid & 31, wid = tid >> 5;
    int wm = wid & 3;
    int wn = wid >> 2;
    int g = lane >> 2, tig = lane & 3;

    const float* xb = x + (size_t)b * 1024000 + n * 64;
    size_t hbase = ((size_t)b * 500 + n) * 2048;
    uint32_t smv = (uint32_t)__cvta_generic_to_shared(vbuf);

    auto issue_l = [&](int l) {
#pragma unroll
        for (int it = 0; it < 2; it++) {
            int i = tid + it * 256;
            int c = i >> 4, tq = (i & 15) * 4;
            const float* src = (l == 0) ? (xb + (size_t)c * 32000 + tq)
                                        : (g_h[l - 1] + hbase + i * 4);
            cp16(smv + (uint32_t)(l * 2304 + c * 72 + tq) * 4, src);
        }
        CP_COMMIT();
    };

    issue_l(0);
    issue_l(1);

    uint32_t a1f[4][4], a2f[8][4];
#pragma unroll
    for (int kk = 0; kk < 4; kk++) {
        a1f[kk][0] = tf32_bits(__ldg(w1 + (wm * 16 + g) * 32 + kk * 8 + tig));
        a1f[kk][1] = tf32_bits(__ldg(w1 + (wm * 16 + g + 8) * 32 + kk * 8 + tig));
        a1f[kk][2] = tf32_bits(__ldg(w1 + (wm * 16 + g) * 32 + kk * 8 + tig + 4));
        a1f[kk][3] = tf32_bits(__ldg(w1 + (wm * 16 + g + 8) * 32 + kk * 8 + tig + 4));
    }
#pragma unroll
    for (int kk = 0; kk < 8; kk++) {
        a2f[kk][0] = tf32_bits(__ldg(w2 + (wm * 16 + g) * 64 + kk * 8 + tig));
        a2f[kk][1] = tf32_bits(__ldg(w2 + (wm * 16 + g + 8) * 64 + kk * 8 + tig));
        a2f[kk][2] = tf32_bits(__ldg(w2 + (wm * 16 + g) * 64 + kk * 8 + tig + 4));
        a2f[kk][3] = tf32_bits(__ldg(w2 + (wm * 16 + g + 8) * 64 + kk * 8 + tig + 4));
    }
    float b1r0 = b1[wm * 16 + g], b1r1 = b1[wm * 16 + g + 8];
    float b2r0 = b2[wm * 16 + g], b2r1 = b2[wm * 16 + g + 8];
    float w3r0 = w3[wm * 16 + g], w3r1 = w3[wm * 16 + g + 8];

    for (int l = 0; l < 5; l++) {
        if (l < 4) asm volatile("cp.async.wait_group 1;");
        else       asm volatile("cp.async.wait_group 0;");
        __syncthreads();
        const float* vb = vbuf + l * 2304;

        // e1 = W1 * relu(h)  (relu + tf32 rounding at fragment load)
        float c1[4][4];
#pragma unroll
        for (int sub = 0; sub < 4; sub++)
#pragma unroll
            for (int k = 0; k < 4; k++) c1[sub][k] = 0.f;
#pragma unroll
        for (int kk = 0; kk < 4; kk++) {
#pragma unroll
            for (int sub = 0; sub < 4; sub++) {
                int col = wn * 32 + sub * 8 + g;
                uint32_t bb0 = tf32_bits(fmaxf(vb[(kk * 8 + tig) * 72 + col], 0.f));
                uint32_t bb1 = tf32_bits(fmaxf(vb[(kk * 8 + tig + 4) * 72 + col], 0.f));
                mma_tf32(c1[sub][0], c1[sub][1], c1[sub][2], c1[sub][3],
                         a1f[kk][0], a1f[kk][1], a1f[kk][2], a1f[kk][3], bb0, bb1);
            }
        }
#pragma unroll
        for (int sub = 0; sub < 4; sub++) {
            int col = wn * 32 + sub * 8 + 2 * tig;
            e1s[(wm * 16 + g) * 72 + col]     = to_tf32(fmaxf(c1[sub][0] + b1r0, 0.f));
            e1s[(wm * 16 + g) * 72 + col + 1] = to_tf32(fmaxf(c1[sub][1] + b1r0, 0.f));
            e1s[(wm * 16 + g + 8) * 72 + col]     = to_tf32(fmaxf(c1[sub][2] + b1r1, 0.f));
            e1s[(wm * 16 + g + 8) * 72 + col + 1] = to_tf32(fmaxf(c1[sub][3] + b1r1, 0.f));
        }
        __syncthreads();

        // e2 = W2 * e1
        float c2[4][4];
#pragma unroll
        for (int sub = 0; sub < 4; sub++)
#pragma unroll
            for (int k = 0; k < 4; k++) c2[sub][k] = 0.f;
#pragma unroll
        for (int kk = 0; kk < 8; kk++) {
#pragma unroll
            for (int sub = 0; sub < 4; sub++) {
                int col = wn * 32 + sub * 8 + g;
                uint32_t bb0 = __float_as_uint(e1s[(kk * 8 + tig) * 72 + col]);
                uint32_t bb1 = __float_as_uint(e1s[(kk * 8 + tig + 4) * 72 + col]);
                mma_tf32(c2[sub][0], c2[sub][1], c2[sub][2], c2[sub][3],
                         a2f[kk][0], a2f[kk][1], a2f[kk][2], a2f[kk][3], bb0, bb1);
            }
        }
        float p[4][2];
#pragma unroll
        for (int sub = 0; sub < 4; sub++) {
            p[sub][0] = w3r0 * fmaxf(c2[sub][0] + b2r0, 0.f) + w3r1 * fmaxf(c2[sub][2] + b2r1, 0.f);
            p[sub][1] = w3r0 * fmaxf(c2[sub][1] + b2r0, 0.f) + w3r1 * fmaxf(c2[sub][3] + b2r1, 0.f);
        }
#pragma unroll
        for (int off = 4; off <= 16; off <<= 1) {
#pragma unroll
            for (int sub = 0; sub < 4; sub++) {
                p[sub][0] += __shfl_xor_sync(0xffffffffu, p[sub][0], off);
                p[sub][1] += __shfl_xor_sync(0xffffffffu, p[sub][1], off);
            }
        }
        if (g == 0) {
#pragma unroll
            for (int sub = 0; sub < 4; sub++) {
                int col = wn * 32 + sub * 8 + 2 * tig;
                red[wm * 64 + col] = p[sub][0];
                red[wm * 64 + col + 1] = p[sub][1];
            }
        }
        // prefetch layer l+2 while the reduction settles
        if (l + 2 < 5) issue_l(l + 2);
        __syncthreads();
        if (tid < 64)
            lgs[l * 64 + tid] = red[tid] + red[64 + tid] + red[128 + tid] + red[192 + tid];
        __syncthreads();
    }

    // softmax over layers (b3 shift is softmax-invariant; omitted)
    if (tid < 64) {
        float lg[5];
        float m = -1e30f;
#pragma unroll
        for (int l = 0; l < 5; l++) {
            lg[l] = lgs[l * 64 + tid];
            m = fmaxf(m, lg[l]);
        }
        float s = 0.f;
#pragma unroll
        for (int l = 0; l < 5; l++) { lg[l] = expf(lg[l] - m); s += lg[l]; }
        float inv = 1.f / s;
#pragma unroll
        for (int l = 0; l < 5; l++) lgs[l * 64 + tid] = lg[l] * inv;
    }
    __syncthreads();

    // weighted sum from smem-resident raw h (relu at read)
    for (int i = tid; i < 2048; i += 256) {
        int c = i >> 6, t = i & 63;
        float s = lgs[t] * fmaxf(vbuf[c * 72 + t], 0.f);
        s += lgs[64 + t]  * fmaxf(vbuf[2304 + c * 72 + t], 0.f);
        s += lgs[128 + t] * fmaxf(vbuf[4608 + c * 72 + t], 0.f);
        s += lgs[192 + t] * fmaxf(vbuf[6912 + c * 72 + t], 0.f);
        s += lgs[256 + t] * fmaxf(vbuf[9216 + c * 72 + t], 0.f);
        out[((size_t)(b * 32 + c) * 500 + n) * 64 + t] = s;
    }
}

// ---------------- launch ----------------
extern "C" void kernel_launch(void* const* d_in, const int* in_sizes, int n_in,
                              void* d_out, int out_size) {
    (void)in_sizes; (void)n_in; (void)out_size;
    const float* x        = (const float*)d_in[0];
    const float* supports = (const float*)d_in[1];
    const float* bn_gamma = (const float*)d_in[2];
    const float* bn_beta  = (const float*)d_in[3];
    const float* res_w    = (const float*)d_in[4];
    const float* res_b    = (const float*)d_in[5];
    const float* aff_w    = (const float*)d_in[6];
    const float* aff_b    = (const float*)d_in[7];
    const float* gate_w   = (const float*)d_in[8];
    const float* gate_b   = (const float*)d_in[9];
    const float* gc_w     = (const float*)d_in[10];
    const float* gc_b     = (const float*)d_in[11];
    const float* attn_w1  = (const float*)d_in[12];
    const float* attn_b1  = (const float*)d_in[13];
    const float* attn_w2  = (const float*)d_in[14];
    const float* attn_b2  = (const float*)d_in[15];
    const float* attn_w3  = (const float*)d_in[16];
    float* out = (float*)d_out;

    cudaFuncSetAttribute(attn_fused, cudaFuncAttributeMaxDynamicSharedMemorySize, 66816);
    cudaFuncSetAttribute(graph_mma, cudaFuncAttributeMaxDynamicSharedMemorySize, 53248);

    prep_weights<<<64, 256>>>(res_w, aff_w, gate_w, gc_w, supports);
    bn_partial<<<dim3(32, 16), 256>>>(x);

    for (int l = 0; l < 4; l++) {
        st_front<<<8000, 256>>>(x, l, bn_gamma + l * 32, bn_beta + l * 32,
                                res_b + l * 32, aff_b + l * 32,
                                gate_b + l * 32, gc_b + l * 32);
        graph_mma<<<dim3(4, 32, 16), 256, 53248>>>(l);
    }
    attn_fused<<<8000, 256, 66816>>>(x, attn_w1, attn_b1, attn_w2, attn_b2, attn_w3, out);
}